// round 4
// baseline (speedup 1.0000x reference)
#include <cuda_runtime.h>
#include <cuda_bf16.h>
#include <cstdint>

// ============================================================================
// BQQLinear collapsed to:  out = quant8(x) @ W + bias
// where W[(k,n),(j,m)] is built from Y_fp/Z_fp sign structure + A coefficients.
//
// Shapes: p=2, j=32, k=32, m=32, l=8, n=32
//   x:    (2,1024, 1024)  -> X (M=2048, K=1024)
//   W:    (K=1024, N=1024),  N index = j*32+m, K index = k*32+n
//   out:  (M=2048, N=1024) fp32
// ============================================================================

#define PP 2
#define JJ 32
#define KK 32
#define MM 32
#define LL 8
#define NN 32

#define GEMM_M 2048
#define GEMM_N 1024
#define GEMM_K 1024

// 4 MB scratch for the effective weight matrix (allocation-free scratch rule).
__device__ float g_W[GEMM_K * GEMM_N];

__device__ __forceinline__ float sgnf(float v) {
    return (v > 0.f) ? 1.f : ((v < 0.f) ? -1.f : 0.f);
}

// ----------------------------------------------------------------------------
// Kernel 1: build W. One block per (j,k) pair; 256 threads.
//   W[(k*32+n)*1024 + (j*32+m)] =
//     sum_p [ A0*ys*zs * (sum_l sgnY[m,l]*sgnZ[l,n])
//           + A1*ys * (sum_l sgnY[m,l])
//           + A2*zs * (sum_l sgnZ[l,n])
//           + A3 ]
//   ys = mean|Y_fp[p,j,k,:,:]| (m*l = 256), zs = mean|Z_fp[p,j,k,:,:]| (l*n = 256)
// ----------------------------------------------------------------------------
__global__ __launch_bounds__(256) void build_w_kernel(
    const float* __restrict__ Y,   // (p,j,k,m,l)
    const float* __restrict__ Z,   // (p,j,k,l,n)
    const float* __restrict__ A)   // (p,j,k,4)
{
    const int j = blockIdx.x;
    const int k = blockIdx.y;
    const int tid = threadIdx.x;   // 0..255

    __shared__ float sY[PP][MM * LL];   // sign(Y), index m*8+l
    __shared__ float sZ[PP][LL * NN];   // sign(Z), index l*32+n
    __shared__ float redY[256], redZ[256];
    __shared__ float ysh[PP], zsh[PP];
    __shared__ float aSh[PP][4];
    __shared__ float Ysum[PP][MM];      // sum_l sgnY[m,l]
    __shared__ float Zsum[PP][NN];      // sum_l sgnZ[l,n]

    #pragma unroll
    for (int p = 0; p < PP; ++p) {
        size_t base = ((size_t)((p * JJ + j) * KK + k)) * 256;
        float y = Y[base + tid];
        float z = Z[base + tid];
        sY[p][tid] = sgnf(y);
        sZ[p][tid] = sgnf(z);
        redY[tid] = fabsf(y);
        redZ[tid] = fabsf(z);
        __syncthreads();
        #pragma unroll
        for (int s = 128; s > 0; s >>= 1) {
            if (tid < s) { redY[tid] += redY[tid + s]; redZ[tid] += redZ[tid + s]; }
            __syncthreads();
        }
        if (tid == 0) {
            ysh[p] = redY[0] * (1.0f / 256.0f);
            zsh[p] = redZ[0] * (1.0f / 256.0f);
        }
        __syncthreads();
    }

    if (tid < PP * 4) {
        int p = tid >> 2, c = tid & 3;
        aSh[p][c] = A[((size_t)(p * JJ + j) * KK + k) * 4 + c];
    }
    if (tid < 64) {
        int p = tid >> 5, m = tid & 31;
        float s = 0.f;
        #pragma unroll
        for (int l = 0; l < LL; ++l) s += sY[p][m * LL + l];
        Ysum[p][m] = s;
    } else if (tid < 128) {
        int t = tid - 64;
        int p = t >> 5, n = t & 31;
        float s = 0.f;
        #pragma unroll
        for (int l = 0; l < LL; ++l) s += sZ[p][l * NN + n];
        Zsum[p][n] = s;
    }
    __syncthreads();

    // 1024 (n,m) entries, 4 per thread; consecutive tid -> consecutive m (coalesced store)
    #pragma unroll
    for (int t = 0; t < 4; ++t) {
        int idx = t * 256 + tid;
        int n = idx >> 5;
        int m = idx & 31;
        float w = 0.f;
        #pragma unroll
        for (int p = 0; p < PP; ++p) {
            float dot = 0.f;
            #pragma unroll
            for (int l = 0; l < LL; ++l)
                dot += sY[p][m * LL + l] * sZ[p][l * NN + n];
            float ys = ysh[p], zs = zsh[p];
            w += aSh[p][0] * ys * zs * dot
               + aSh[p][1] * ys * Ysum[p][m]
               + aSh[p][2] * zs * Zsum[p][n]
               + aSh[p][3];
        }
        g_W[(size_t)(k * NN + n) * GEMM_N + (j * MM + m)] = w;
    }
}

// ----------------------------------------------------------------------------
// Kernel 2: SGEMM  out[M,N] = quant8(X)[M,K] @ W[K,N] + bias[N]
// Tiles: BM=128, BN=128, BK=8; 256 threads; 8x8 microtile per thread.
// quant8 fused into A-tile load; bias fused into epilogue.
// ----------------------------------------------------------------------------
__global__ __launch_bounds__(256) void gemm_kernel(
    const float* __restrict__ X,          // (M, K)
    const float* __restrict__ bias,       // (N)
    const float* __restrict__ act_scale,  // (1)
    float* __restrict__ out)              // (M, N)
{
    const int bx = blockIdx.x;   // N tile (0..7)
    const int by = blockIdx.y;   // M tile (0..15)
    const int tid = threadIdx.x;

    __shared__ float As[8][128];   // [k][m]
    __shared__ float Bs[8][128];   // [k][n]

    const float s = fmaxf(fabsf(act_scale[0]), 1e-8f);
    const float inv_s = 1.0f / s;

    // A-tile load mapping: 128 rows (M) x 8 cols (K); 2 float4 per row
    const int aRow = tid >> 1;            // 0..127
    const int aCol = (tid & 1) << 2;      // 0 or 4
    // B-tile load mapping: 8 rows (K) x 128 cols (N); float4 each
    const int bRow = tid >> 5;            // 0..7
    const int bCol = (tid & 31) << 2;     // 0..124

    const float* Aptr = X + (size_t)(by * 128 + aRow) * GEMM_K + aCol;
    const float* Bptr = g_W + (size_t)bRow * GEMM_N + bx * 128 + bCol;

    const int ty = (tid >> 4) << 3;       // 0..120 step 8
    const int tx = (tid & 15) << 3;       // 0..120 step 8

    float acc[8][8];
    #pragma unroll
    for (int i = 0; i < 8; ++i)
        #pragma unroll
        for (int jn = 0; jn < 8; ++jn) acc[i][jn] = 0.f;

    for (int k0 = 0; k0 < GEMM_K; k0 += 8) {
        float4 av = *(const float4*)(Aptr + k0);
        // quant8: q = clip(rint(x/s), -127, 127); X = q*s  (rintf = half-to-even)
        float q0 = fminf(fmaxf(rintf(av.x * inv_s), -127.f), 127.f) * s;
        float q1 = fminf(fmaxf(rintf(av.y * inv_s), -127.f), 127.f) * s;
        float q2 = fminf(fmaxf(rintf(av.z * inv_s), -127.f), 127.f) * s;
        float q3 = fminf(fmaxf(rintf(av.w * inv_s), -127.f), 127.f) * s;
        As[aCol + 0][aRow] = q0;
        As[aCol + 1][aRow] = q1;
        As[aCol + 2][aRow] = q2;
        As[aCol + 3][aRow] = q3;

        *(float4*)&Bs[bRow][bCol] = *(const float4*)(Bptr + (size_t)k0 * GEMM_N);
        __syncthreads();

        #pragma unroll
        for (int kk = 0; kk < 8; ++kk) {
            float ar[8], br[8];
            *(float4*)&ar[0] = *(const float4*)&As[kk][ty];
            *(float4*)&ar[4] = *(const float4*)&As[kk][ty + 4];
            *(float4*)&br[0] = *(const float4*)&Bs[kk][tx];
            *(float4*)&br[4] = *(const float4*)&Bs[kk][tx + 4];
            #pragma unroll
            for (int i = 0; i < 8; ++i)
                #pragma unroll
                for (int jn = 0; jn < 8; ++jn)
                    acc[i][jn] += ar[i] * br[jn];
        }
        __syncthreads();
    }

    // Epilogue: add bias, write out
    #pragma unroll
    for (int i = 0; i < 8; ++i) {
        float* orow = out + (size_t)(by * 128 + ty + i) * GEMM_N + bx * 128 + tx;
        const float* brow = bias + bx * 128 + tx;
        #pragma unroll
        for (int jn = 0; jn < 8; ++jn)
            orow[jn] = acc[i][jn] + brow[jn];
    }
}

// ----------------------------------------------------------------------------
// Launch
// Inputs (metadata order): x, Y_fp, Z_fp, A, bias, act_scale
// ----------------------------------------------------------------------------
extern "C" void kernel_launch(void* const* d_in, const int* in_sizes, int n_in,
                              void* d_out, int out_size) {
    const float* x         = (const float*)d_in[0];
    const float* Y_fp      = (const float*)d_in[1];
    const float* Z_fp      = (const float*)d_in[2];
    const float* A         = (const float*)d_in[3];
    const float* bias      = (const float*)d_in[4];
    const float* act_scale = (const float*)d_in[5];
    float* out = (float*)d_out;

    dim3 gridW(JJ, KK);
    build_w_kernel<<<gridW, 256>>>(Y_fp, Z_fp, A);

    dim3 gridG(GEMM_N / 128, GEMM_M / 128);
    gemm_kernel<<<gridG, 256>>>(x, bias, act_scale, out);
}

// round 6
// speedup vs baseline: 3.4519x; 3.4519x over previous
#include <cuda_runtime.h>
#include <cuda_bf16.h>
#include <cstdint>

// ============================================================================
// BQQLinear collapsed to:  out = quant8(x) @ W + bias
//   quant8(x) = s * q,  q integer in [-127,127]  -> q exact in bf16
//   W (fp32)  = Whi(bf16) + Wlo(bf16 residual)
//   out = s * ( q @ Whi + q @ Wlo ) + bias
// GEMM via mma.sync.m16n8k16 bf16 (HMMA) -- compute_103-safe PTX.
//
// Shapes: p=2, j=32, k=32, m=32, l=8, n=32
//   X: (M=2048, K=1024), Wt (N=1024, K=1024) K-major
// ============================================================================

#define PP 2
#define JJ 32
#define KK 32
#define MM 32
#define LL 8
#define NN 32

#define GEMM_M 2048
#define GEMM_N 1024
#define GEMM_K 1024

#define BM 128
#define BN 128
#define BKC 32
#define NCHUNK (GEMM_K / BKC)      // 32

#define SM_STRIDE 40               // bf16 elems per smem row (32 + 8 pad) -> 80 B
#define TILE_SM_BYTES (128 * SM_STRIDE * 2)     // 10240
#define STAGE_BYTES (3 * TILE_SM_BYTES)         // A + Bhi + Blo = 30720
#define DSMEM_BYTES (2 * STAGE_BYTES + 256)     // 61696

// Device-global scratch (allocation-free rule)
__device__ __nv_bfloat16 g_Aq [GEMM_M * GEMM_K];   // 4 MB
__device__ __nv_bfloat16 g_Whi[GEMM_N * GEMM_K];   // 2 MB (N-major, K contiguous)
__device__ __nv_bfloat16 g_Wlo[GEMM_N * GEMM_K];   // 2 MB

// ---------------------------------------------------------------------------
// helpers
// ---------------------------------------------------------------------------
__device__ __forceinline__ uint32_t smem_u32(const void* p) {
    uint32_t a;
    asm("{ .reg .u64 t; cvta.to.shared.u64 t, %1; cvt.u32.u64 %0, t; }"
        : "=r"(a) : "l"(p));
    return a;
}

__device__ __forceinline__ void ldsm_x4(uint32_t* r, uint32_t addr) {
    asm volatile("ldmatrix.sync.aligned.m8n8.x4.shared.b16 {%0,%1,%2,%3}, [%4];"
                 : "=r"(r[0]), "=r"(r[1]), "=r"(r[2]), "=r"(r[3]) : "r"(addr));
}

__device__ __forceinline__ void mma16816(float* c, const uint32_t* a,
                                         const uint32_t* b) {
    asm volatile(
        "mma.sync.aligned.m16n8k16.row.col.f32.bf16.bf16.f32 "
        "{%0,%1,%2,%3}, {%4,%5,%6,%7}, {%8,%9}, {%0,%1,%2,%3};"
        : "+f"(c[0]), "+f"(c[1]), "+f"(c[2]), "+f"(c[3])
        : "r"(a[0]), "r"(a[1]), "r"(a[2]), "r"(a[3]), "r"(b[0]), "r"(b[1]));
}

#define CP_ASYNC16(dst, src) \
    asm volatile("cp.async.cg.shared.global [%0], [%1], 16;" \
                 :: "r"(dst), "l"(src) : "memory")
#define CP_COMMIT() asm volatile("cp.async.commit_group;" ::: "memory")
#define CP_WAIT(n)  asm volatile("cp.async.wait_group %0;" :: "n"(n) : "memory")

__device__ __forceinline__ float sgnf(float v) {
    return (v > 0.f) ? 1.f : ((v < 0.f) ? -1.f : 0.f);
}

// ----------------------------------------------------------------------------
// Kernel 1: quantize activations -> bf16 integers q
// ----------------------------------------------------------------------------
__global__ __launch_bounds__(256) void quant_kernel(
    const float* __restrict__ x,
    const float* __restrict__ act_scale,
    __nv_bfloat16* __restrict__ qout)
{
    const float s = fmaxf(fabsf(act_scale[0]), 1e-8f);
    const float inv = 1.0f / s;
    int i = blockIdx.x * blockDim.x + threadIdx.x;   // over float4s
    float4 v = ((const float4*)x)[i];
    float q0 = fminf(fmaxf(rintf(v.x * inv), -127.f), 127.f);
    float q1 = fminf(fmaxf(rintf(v.y * inv), -127.f), 127.f);
    float q2 = fminf(fmaxf(rintf(v.z * inv), -127.f), 127.f);
    float q3 = fminf(fmaxf(rintf(v.w * inv), -127.f), 127.f);
    __nv_bfloat162* o = (__nv_bfloat162*)qout;
    o[2 * i + 0] = __floats2bfloat162_rn(q0, q1);
    o[2 * i + 1] = __floats2bfloat162_rn(q2, q3);
}

// ----------------------------------------------------------------------------
// Kernel 2: build Wt (N-major) as bf16 hi + lo.
//   Wt[n_glob = j*32+m][k_glob = k*32+n] = W[(k,n),(j,m)]
// ----------------------------------------------------------------------------
__global__ __launch_bounds__(256) void build_w_kernel(
    const float* __restrict__ Y,   // (p,j,k,m,l)
    const float* __restrict__ Z,   // (p,j,k,l,n)
    const float* __restrict__ A)   // (p,j,k,4)
{
    const int j = blockIdx.x;
    const int k = blockIdx.y;
    const int tid = threadIdx.x;

    __shared__ float sY[PP][MM * LL];
    __shared__ float sZ[PP][LL * NN];
    __shared__ float redY[256], redZ[256];
    __shared__ float ysh[PP], zsh[PP];
    __shared__ float aSh[PP][4];
    __shared__ float Ysum[PP][MM];
    __shared__ float Zsum[PP][NN];

    #pragma unroll
    for (int p = 0; p < PP; ++p) {
        size_t base = ((size_t)((p * JJ + j) * KK + k)) * 256;
        float y = Y[base + tid];
        float z = Z[base + tid];
        sY[p][tid] = sgnf(y);
        sZ[p][tid] = sgnf(z);
        redY[tid] = fabsf(y);
        redZ[tid] = fabsf(z);
        __syncthreads();
        #pragma unroll
        for (int s = 128; s > 0; s >>= 1) {
            if (tid < s) { redY[tid] += redY[tid + s]; redZ[tid] += redZ[tid + s]; }
            __syncthreads();
        }
        if (tid == 0) {
            ysh[p] = redY[0] * (1.0f / 256.0f);
            zsh[p] = redZ[0] * (1.0f / 256.0f);
        }
        __syncthreads();
    }

    if (tid < PP * 4) {
        int p = tid >> 2, c = tid & 3;
        aSh[p][c] = A[((size_t)(p * JJ + j) * KK + k) * 4 + c];
    }
    if (tid < 64) {
        int p = tid >> 5, m = tid & 31;
        float s = 0.f;
        #pragma unroll
        for (int l = 0; l < LL; ++l) s += sY[p][m * LL + l];
        Ysum[p][m] = s;
    } else if (tid < 128) {
        int t = tid - 64;
        int p = t >> 5, n = t & 31;
        float s = 0.f;
        #pragma unroll
        for (int l = 0; l < LL; ++l) s += sZ[p][l * NN + n];
        Zsum[p][n] = s;
    }
    __syncthreads();

    #pragma unroll
    for (int t = 0; t < 4; ++t) {
        int idx = t * 256 + tid;
        int m = idx >> 5;
        int n = idx & 31;
        float w = 0.f;
        #pragma unroll
        for (int p = 0; p < PP; ++p) {
            float dot = 0.f;
            #pragma unroll
            for (int l = 0; l < LL; ++l)
                dot += sY[p][m * LL + l] * sZ[p][l * NN + n];
            float ys = ysh[p], zs = zsh[p];
            w += aSh[p][0] * ys * zs * dot
               + aSh[p][1] * ys * Ysum[p][m]
               + aSh[p][2] * zs * Zsum[p][n]
               + aSh[p][3];
        }
        size_t off = (size_t)(j * MM + m) * GEMM_K + (k * NN + n);
        __nv_bfloat16 hi = __float2bfloat16(w);
        float lo = w - __bfloat162float(hi);
        g_Whi[off] = hi;
        g_Wlo[off] = __float2bfloat16(lo);
    }
}

// ----------------------------------------------------------------------------
// Kernel 3: mma.sync GEMM  out = s * (q @ (Whi + Wlo)) + bias
// CTA 128x128, BK=32, 8 warps (warp tile 64x32), cp.async double buffering.
// ----------------------------------------------------------------------------
extern __shared__ char dynsmem[];

__global__ __launch_bounds__(256, 1) void gemm_mma_kernel(
    const float* __restrict__ bias,
    const float* __restrict__ act_scale,
    float* __restrict__ out)
{
    const int tid  = threadIdx.x;
    const int wid  = tid >> 5;
    const int lane = tid & 31;
    const int n0 = blockIdx.x * BN;
    const int m0 = blockIdx.y * BM;

    const int warp_m = wid & 1;    // 0..1 -> rows warp_m*64
    const int warp_n = wid >> 1;   // 0..3 -> cols warp_n*32

    // 16B-align the dynamic smem base
    uint32_t raw = smem_u32(dynsmem);
    uint32_t sbase = (raw + 127u) & ~127u;

    const __nv_bfloat16* Aq = g_Aq  + (size_t)m0 * GEMM_K;
    const __nv_bfloat16* Wh = g_Whi + (size_t)n0 * GEMM_K;
    const __nv_bfloat16* Wl = g_Wlo + (size_t)n0 * GEMM_K;

    // ---- async loader: chunk c -> stage buf ----
    auto load_chunk = [&](int c, int buf) {
        const int k0 = c * BKC;
        uint32_t base = sbase + buf * STAGE_BYTES;
        #pragma unroll
        for (int it = 0; it < 2; ++it) {
            int s = it * 256 + tid;       // 0..511 segments of 16B
            int row = s >> 2;             // 0..127
            int seg = s & 3;              // 0..3
            uint32_t dst = base + (uint32_t)(row * (SM_STRIDE * 2) + seg * 16);
            size_t goff = (size_t)row * GEMM_K + k0 + seg * 8;
            CP_ASYNC16(dst,                          Aq + goff);
            CP_ASYNC16(dst + TILE_SM_BYTES,          Wh + goff);
            CP_ASYNC16(dst + 2 * TILE_SM_BYTES,      Wl + goff);
        }
    };

    float acc[4][4][4];
    #pragma unroll
    for (int mi = 0; mi < 4; ++mi)
        #pragma unroll
        for (int ni = 0; ni < 4; ++ni)
            #pragma unroll
            for (int q = 0; q < 4; ++q) acc[mi][ni][q] = 0.f;

    // Per-thread ldmatrix source addresses (fixed per buf; offsets vary by ks)
    // A: thread -> row (lane&15), k-offset (lane>>4)*8
    const int aRowT = warp_m * 64 + (lane & 15);
    const int aKT   = (lane >> 4) * 8;
    // B: grp = lane>>3: {nt-half, k-half}; ln = lane&7
    const int grp = lane >> 3, ln = lane & 7;
    const int bRowBase = warp_n * 32 + (grp >> 1) * 8 + ln;  // + half*16
    const int bKT = (grp & 1) * 8;

    // prologue
    load_chunk(0, 0);
    CP_COMMIT();

    for (int c = 0; c < NCHUNK; ++c) {
        const int buf = c & 1;
        if (c + 1 < NCHUNK) {
            load_chunk(c + 1, buf ^ 1);
            CP_COMMIT();
            CP_WAIT(1);
        } else {
            CP_WAIT(0);
        }
        __syncthreads();

        const uint32_t aTile = sbase + buf * STAGE_BYTES;
        const uint32_t hTile = aTile + TILE_SM_BYTES;
        const uint32_t lTile = aTile + 2 * TILE_SM_BYTES;

        #pragma unroll
        for (int ks = 0; ks < BKC; ks += 16) {
            uint32_t afrag[4][4];
            #pragma unroll
            for (int mi = 0; mi < 4; ++mi) {
                uint32_t addr = aTile +
                    (uint32_t)((aRowT + mi * 16) * (SM_STRIDE * 2) + (ks + aKT) * 2);
                ldsm_x4(afrag[mi], addr);
            }
            uint32_t bh[4][2], bl[4][2];
            #pragma unroll
            for (int half = 0; half < 2; ++half) {
                uint32_t r[4];
                uint32_t addr = hTile +
                    (uint32_t)((bRowBase + half * 16) * (SM_STRIDE * 2) + (ks + bKT) * 2);
                ldsm_x4(r, addr);
                bh[2 * half][0] = r[0]; bh[2 * half][1] = r[1];
                bh[2 * half + 1][0] = r[2]; bh[2 * half + 1][1] = r[3];
                uint32_t addr2 = lTile +
                    (uint32_t)((bRowBase + half * 16) * (SM_STRIDE * 2) + (ks + bKT) * 2);
                ldsm_x4(r, addr2);
                bl[2 * half][0] = r[0]; bl[2 * half][1] = r[1];
                bl[2 * half + 1][0] = r[2]; bl[2 * half + 1][1] = r[3];
            }
            #pragma unroll
            for (int mi = 0; mi < 4; ++mi)
                #pragma unroll
                for (int ni = 0; ni < 4; ++ni) {
                    mma16816(acc[mi][ni], afrag[mi], bh[ni]);
                    mma16816(acc[mi][ni], afrag[mi], bl[ni]);
                }
        }
        __syncthreads();
    }

    // ---- epilogue: out = acc*s + bias ----
    const float sval = fmaxf(fabsf(act_scale[0]), 1e-8f);
    const int gID = lane >> 2;     // 0..7
    const int tig = lane & 3;      // 0..3

    #pragma unroll
    for (int mi = 0; mi < 4; ++mi) {
        const int rbase = m0 + warp_m * 64 + mi * 16 + gID;
        #pragma unroll
        for (int ni = 0; ni < 4; ++ni) {
            const int col = n0 + warp_n * 32 + ni * 8 + 2 * tig;
            const float b0 = bias[col], b1 = bias[col + 1];
            float2 v0, v1;
            v0.x = acc[mi][ni][0] * sval + b0;
            v0.y = acc[mi][ni][1] * sval + b1;
            v1.x = acc[mi][ni][2] * sval + b0;
            v1.y = acc[mi][ni][3] * sval + b1;
            *(float2*)(out + (size_t)rbase * GEMM_N + col) = v0;
            *(float2*)(out + (size_t)(rbase + 8) * GEMM_N + col) = v1;
        }
    }
}

// ----------------------------------------------------------------------------
// Launch. Inputs (metadata order): x, Y_fp, Z_fp, A, bias, act_scale
// ----------------------------------------------------------------------------
extern "C" void kernel_launch(void* const* d_in, const int* in_sizes, int n_in,
                              void* d_out, int out_size) {
    const float* x         = (const float*)d_in[0];
    const float* Y_fp      = (const float*)d_in[1];
    const float* Z_fp      = (const float*)d_in[2];
    const float* A         = (const float*)d_in[3];
    const float* bias      = (const float*)d_in[4];
    const float* act_scale = (const float*)d_in[5];
    float* out = (float*)d_out;

    __nv_bfloat16* aq;
    cudaGetSymbolAddress((void**)&aq, g_Aq);

    cudaFuncSetAttribute(gemm_mma_kernel,
                         cudaFuncAttributeMaxDynamicSharedMemorySize, DSMEM_BYTES);

    quant_kernel<<<(GEMM_M * GEMM_K / 4) / 256, 256>>>(x, act_scale, aq);

    dim3 gridW(JJ, KK);
    build_w_kernel<<<gridW, 256>>>(Y_fp, Z_fp, A);

    dim3 gridG(GEMM_N / BN, GEMM_M / BM);
    gemm_mma_kernel<<<gridG, 256, DSMEM_BYTES>>>(bias, act_scale, out);
}

// round 7
// speedup vs baseline: 4.3648x; 1.2645x over previous
#include <cuda_runtime.h>
#include <cuda_fp16.h>
#include <cstdint>

// ============================================================================
// BQQLinear collapsed to:  out = quant8(x) @ W + bias
//   quant8(x) = s * q,  q integer in [-127,127]  -> q exact in fp16
//   W (fp32) -> fp16 (11-bit significand; avg elem err 2^-12 -> out ~1e-4)
//   out = s * ( q @ W_fp16 ) + bias   via mma.sync m16n8k16 f16, fp32 accum
//
// Shapes: p=2, j=32, k=32, m=32, l=8, n=32
//   X: (M=2048, K=1024), Wt (N=1024, K=1024) K-major
// ============================================================================

#define PP 2
#define JJ 32
#define KK 32
#define MM 32
#define LL 8
#define NN 32

#define GEMM_M 2048
#define GEMM_N 1024
#define GEMM_K 1024

#define BM 128
#define BN 128
#define BKC 64
#define NCHUNK (GEMM_K / BKC)      // 16

#define SM_STRIDE 72               // fp16 elems per smem row (64 + 8 pad) -> 144 B
#define TILE_SM_BYTES (128 * SM_STRIDE * 2)     // 18432
#define STAGE_BYTES (2 * TILE_SM_BYTES)         // A + B = 36864
#define NSTAGE 3
#define DSMEM_BYTES (NSTAGE * STAGE_BYTES + 256)

// Device-global scratch (allocation-free rule)
__device__ __half g_Aq[GEMM_M * GEMM_K];   // 4 MB: fp16(q)
__device__ __half g_Wt[GEMM_N * GEMM_K];   // 2 MB: Wt fp16 (N-major, K contiguous)

// ---------------------------------------------------------------------------
// helpers
// ---------------------------------------------------------------------------
__device__ __forceinline__ uint32_t smem_u32(const void* p) {
    uint32_t a;
    asm("{ .reg .u64 t; cvta.to.shared.u64 t, %1; cvt.u32.u64 %0, t; }"
        : "=r"(a) : "l"(p));
    return a;
}

__device__ __forceinline__ void ldsm_x4(uint32_t* r, uint32_t addr) {
    asm volatile("ldmatrix.sync.aligned.m8n8.x4.shared.b16 {%0,%1,%2,%3}, [%4];"
                 : "=r"(r[0]), "=r"(r[1]), "=r"(r[2]), "=r"(r[3]) : "r"(addr));
}

__device__ __forceinline__ void mma16816(float* c, const uint32_t* a,
                                         const uint32_t* b) {
    asm volatile(
        "mma.sync.aligned.m16n8k16.row.col.f32.f16.f16.f32 "
        "{%0,%1,%2,%3}, {%4,%5,%6,%7}, {%8,%9}, {%0,%1,%2,%3};"
        : "+f"(c[0]), "+f"(c[1]), "+f"(c[2]), "+f"(c[3])
        : "r"(a[0]), "r"(a[1]), "r"(a[2]), "r"(a[3]), "r"(b[0]), "r"(b[1]));
}

#define CP_ASYNC16(dst, src) \
    asm volatile("cp.async.cg.shared.global [%0], [%1], 16;" \
                 :: "r"(dst), "l"(src) : "memory")
#define CP_COMMIT() asm volatile("cp.async.commit_group;" ::: "memory")
#define CP_WAIT(n)  asm volatile("cp.async.wait_group %0;" :: "n"(n) : "memory")

__device__ __forceinline__ float sgnf(float v) {
    return (v > 0.f) ? 1.f : ((v < 0.f) ? -1.f : 0.f);
}

// ----------------------------------------------------------------------------
// Kernel 1: quantize activations -> fp16 integers q  (4 float4 per thread)
// ----------------------------------------------------------------------------
__global__ __launch_bounds__(256) void quant_kernel(
    const float* __restrict__ x,
    const float* __restrict__ act_scale,
    __half* __restrict__ qout)
{
    const float s = fmaxf(fabsf(act_scale[0]), 1e-8f);
    const float inv = 1.0f / s;
    const int base = (blockIdx.x * 256 + threadIdx.x) * 4;  // float4 index
    const float4* xv = (const float4*)x;
    __half2* o = (__half2*)qout;
    #pragma unroll
    for (int t = 0; t < 4; ++t) {
        int i = base + t;
        float4 v = xv[i];
        float q0 = fminf(fmaxf(rintf(v.x * inv), -127.f), 127.f);
        float q1 = fminf(fmaxf(rintf(v.y * inv), -127.f), 127.f);
        float q2 = fminf(fmaxf(rintf(v.z * inv), -127.f), 127.f);
        float q3 = fminf(fmaxf(rintf(v.w * inv), -127.f), 127.f);
        o[2 * i + 0] = __floats2half2_rn(q0, q1);
        o[2 * i + 1] = __floats2half2_rn(q2, q3);
    }
}

// ----------------------------------------------------------------------------
// Kernel 2: build Wt (N-major) as fp16.
//   Wt[n_glob = j*32+m][k_glob = k*32+n] = W[(k,n),(j,m)]
// ----------------------------------------------------------------------------
__global__ __launch_bounds__(256) void build_w_kernel(
    const float* __restrict__ Y,   // (p,j,k,m,l)
    const float* __restrict__ Z,   // (p,j,k,l,n)
    const float* __restrict__ A)   // (p,j,k,4)
{
    const int j = blockIdx.x;
    const int k = blockIdx.y;
    const int tid = threadIdx.x;

    __shared__ float sY[PP][MM * LL];
    __shared__ float sZ[PP][LL * NN];
    __shared__ float redY[256], redZ[256];
    __shared__ float ysh[PP], zsh[PP];
    __shared__ float aSh[PP][4];
    __shared__ float Ysum[PP][MM];
    __shared__ float Zsum[PP][NN];

    #pragma unroll
    for (int p = 0; p < PP; ++p) {
        size_t base = ((size_t)((p * JJ + j) * KK + k)) * 256;
        float y = Y[base + tid];
        float z = Z[base + tid];
        sY[p][tid] = sgnf(y);
        sZ[p][tid] = sgnf(z);
        redY[tid] = fabsf(y);
        redZ[tid] = fabsf(z);
        __syncthreads();
        #pragma unroll
        for (int s = 128; s > 0; s >>= 1) {
            if (tid < s) { redY[tid] += redY[tid + s]; redZ[tid] += redZ[tid + s]; }
            __syncthreads();
        }
        if (tid == 0) {
            ysh[p] = redY[0] * (1.0f / 256.0f);
            zsh[p] = redZ[0] * (1.0f / 256.0f);
        }
        __syncthreads();
    }

    if (tid < PP * 4) {
        int p = tid >> 2, c = tid & 3;
        aSh[p][c] = A[((size_t)(p * JJ + j) * KK + k) * 4 + c];
    }
    if (tid < 64) {
        int p = tid >> 5, m = tid & 31;
        float s = 0.f;
        #pragma unroll
        for (int l = 0; l < LL; ++l) s += sY[p][m * LL + l];
        Ysum[p][m] = s;
    } else if (tid < 128) {
        int t = tid - 64;
        int p = t >> 5, n = t & 31;
        float s = 0.f;
        #pragma unroll
        for (int l = 0; l < LL; ++l) s += sZ[p][l * NN + n];
        Zsum[p][n] = s;
    }
    __syncthreads();

    #pragma unroll
    for (int t = 0; t < 4; ++t) {
        int idx = t * 256 + tid;
        int m = idx >> 5;
        int n = idx & 31;
        float w = 0.f;
        #pragma unroll
        for (int p = 0; p < PP; ++p) {
            float dot = 0.f;
            #pragma unroll
            for (int l = 0; l < LL; ++l)
                dot += sY[p][m * LL + l] * sZ[p][l * NN + n];
            float ys = ysh[p], zs = zsh[p];
            w += aSh[p][0] * ys * zs * dot
               + aSh[p][1] * ys * Ysum[p][m]
               + aSh[p][2] * zs * Zsum[p][n]
               + aSh[p][3];
        }
        size_t off = (size_t)(j * MM + m) * GEMM_K + (k * NN + n);
        g_Wt[off] = __float2half_rn(w);
    }
}

// ----------------------------------------------------------------------------
// Kernel 3: mma.sync GEMM  out = s * (q @ Wt^T) + bias
// CTA 128x128, BK=64, 8 warps (warp tile 64x32), 3-stage cp.async pipeline.
// ----------------------------------------------------------------------------
extern __shared__ char dynsmem[];

__global__ __launch_bounds__(256, 1) void gemm_mma_kernel(
    const float* __restrict__ bias,
    const float* __restrict__ act_scale,
    float* __restrict__ out)
{
    const int tid  = threadIdx.x;
    const int wid  = tid >> 5;
    const int lane = tid & 31;
    const int n0 = blockIdx.x * BN;
    const int m0 = blockIdx.y * BM;

    const int warp_m = wid & 1;    // rows warp_m*64
    const int warp_n = wid >> 1;   // cols warp_n*32

    uint32_t raw = smem_u32(dynsmem);
    uint32_t sbase = (raw + 127u) & ~127u;

    const __half* Aq = g_Aq + (size_t)m0 * GEMM_K;
    const __half* Wp = g_Wt + (size_t)n0 * GEMM_K;

    // ---- async loader: chunk c -> stage buf ----
    // per tile: 128 rows x 8 segments of 16B (64 fp16 data, row stride 144B)
    auto load_chunk = [&](int c, int buf) {
        const int k0 = c * BKC;
        uint32_t base = sbase + buf * STAGE_BYTES;
        #pragma unroll
        for (int it = 0; it < 4; ++it) {
            int s = it * 256 + tid;       // 0..1023
            int row = s >> 3;             // 0..127
            int seg = s & 7;              // 0..7
            uint32_t dst = base + (uint32_t)(row * (SM_STRIDE * 2) + seg * 16);
            size_t goff = (size_t)row * GEMM_K + k0 + seg * 8;
            CP_ASYNC16(dst,                 Aq + goff);
            CP_ASYNC16(dst + TILE_SM_BYTES, Wp + goff);
        }
    };

    float acc[4][4][4];
    #pragma unroll
    for (int mi = 0; mi < 4; ++mi)
        #pragma unroll
        for (int ni = 0; ni < 4; ++ni)
            #pragma unroll
            for (int q = 0; q < 4; ++q) acc[mi][ni][q] = 0.f;

    // ldmatrix thread mappings
    const int aRowT = warp_m * 64 + (lane & 15);
    const int aKT   = (lane >> 4) * 8;
    const int grp = lane >> 3, ln = lane & 7;
    const int bRowBase = warp_n * 32 + (grp >> 1) * 8 + ln;  // + half*16
    const int bKT = (grp & 1) * 8;

    // prologue: stages 0 and 1
    load_chunk(0, 0);
    CP_COMMIT();
    load_chunk(1, 1);
    CP_COMMIT();

    for (int c = 0; c < NCHUNK; ++c) {
        const int buf = c % NSTAGE;
        if (c == NCHUNK - 1) { CP_WAIT(0); } else { CP_WAIT(1); }
        __syncthreads();

        if (c + 2 < NCHUNK) {
            load_chunk(c + 2, (c + 2) % NSTAGE);
            CP_COMMIT();
        }

        const uint32_t aTile = sbase + buf * STAGE_BYTES;
        const uint32_t bTile = aTile + TILE_SM_BYTES;

        #pragma unroll
        for (int ks = 0; ks < BKC; ks += 16) {
            uint32_t afrag[4][4];
            #pragma unroll
            for (int mi = 0; mi < 4; ++mi) {
                uint32_t addr = aTile +
                    (uint32_t)((aRowT + mi * 16) * (SM_STRIDE * 2) + (ks + aKT) * 2);
                ldsm_x4(afrag[mi], addr);
            }
            uint32_t bf[4][2];
            #pragma unroll
            for (int half = 0; half < 2; ++half) {
                uint32_t r[4];
                uint32_t addr = bTile +
                    (uint32_t)((bRowBase + half * 16) * (SM_STRIDE * 2) + (ks + bKT) * 2);
                ldsm_x4(r, addr);
                bf[2 * half][0] = r[0]; bf[2 * half][1] = r[1];
                bf[2 * half + 1][0] = r[2]; bf[2 * half + 1][1] = r[3];
            }
            #pragma unroll
            for (int mi = 0; mi < 4; ++mi)
                #pragma unroll
                for (int ni = 0; ni < 4; ++ni)
                    mma16816(acc[mi][ni], afrag[mi], bf[ni]);
        }
    }

    // ---- epilogue: out = acc*s + bias ----
    const float sval = fmaxf(fabsf(act_scale[0]), 1e-8f);
    const int gID = lane >> 2;
    const int tig = lane & 3;

    #pragma unroll
    for (int mi = 0; mi < 4; ++mi) {
        const int rbase = m0 + warp_m * 64 + mi * 16 + gID;
        #pragma unroll
        for (int ni = 0; ni < 4; ++ni) {
            const int col = n0 + warp_n * 32 + ni * 8 + 2 * tig;
            const float b0 = bias[col], b1 = bias[col + 1];
            float2 v0, v1;
            v0.x = acc[mi][ni][0] * sval + b0;
            v0.y = acc[mi][ni][1] * sval + b1;
            v1.x = acc[mi][ni][2] * sval + b0;
            v1.y = acc[mi][ni][3] * sval + b1;
            *(float2*)(out + (size_t)rbase * GEMM_N + col) = v0;
            *(float2*)(out + (size_t)(rbase + 8) * GEMM_N + col) = v1;
        }
    }
}

// ----------------------------------------------------------------------------
// Launch. Inputs (metadata order): x, Y_fp, Z_fp, A, bias, act_scale
// ----------------------------------------------------------------------------
extern "C" void kernel_launch(void* const* d_in, const int* in_sizes, int n_in,
                              void* d_out, int out_size) {
    const float* x         = (const float*)d_in[0];
    const float* Y_fp      = (const float*)d_in[1];
    const float* Z_fp      = (const float*)d_in[2];
    const float* A         = (const float*)d_in[3];
    const float* bias      = (const float*)d_in[4];
    const float* act_scale = (const float*)d_in[5];
    float* out = (float*)d_out;

    __half* aq;
    cudaGetSymbolAddress((void**)&aq, g_Aq);

    cudaFuncSetAttribute(gemm_mma_kernel,
                         cudaFuncAttributeMaxDynamicSharedMemorySize, DSMEM_BYTES);

    // quantize x -> fp16 q   (2048*1024 elems / (256 thr * 16 elems) = 512 blocks)
    quant_kernel<<<512, 256>>>(x, act_scale, aq);

    dim3 gridW(JJ, KK);
    build_w_kernel<<<gridW, 256>>>(Y_fp, Z_fp, A);

    dim3 gridG(GEMM_N / BN, GEMM_M / BM);
    gemm_mma_kernel<<<gridG, 256, DSMEM_BYTES>>>(bias, act_scale, out);
}

// round 8
// speedup vs baseline: 4.6160x; 1.0576x over previous
#include <cuda_runtime.h>
#include <cuda_fp16.h>
#include <cstdint>

// ============================================================================
// BQQLinear collapsed to:  out = quant8(x) @ W + bias
//   quant8(x) = s * q,  q integer in [-127,127]  -> q exact in fp16
//   W (fp32) -> fp16 ;  out = s * ( q @ W_fp16 ) + bias
// GEMM via mma.sync m16n8k16 f16 (fp32 accum), compute_103-safe PTX.
//   X: (M=2048, K=1024), Wt (N=1024, K=1024) K-major
// ============================================================================

#define PP 2
#define JJ 32
#define KK 32
#define MM 32
#define LL 8
#define NN 32

#define GEMM_M 2048
#define GEMM_N 1024
#define GEMM_K 1024

#define BM 128
#define BN 64
#define BKC 32
#define NCHUNK (GEMM_K / BKC)      // 32

#define SM_STRIDE 40               // fp16 elems per smem row (32 + 8 pad) -> 80 B
#define A_TILE_BYTES (BM * SM_STRIDE * 2)             // 10240
#define B_TILE_BYTES (BN * SM_STRIDE * 2)             // 5120
#define STAGE_BYTES (A_TILE_BYTES + B_TILE_BYTES)     // 15360
#define NSTAGE 4
#define DSMEM_BYTES (NSTAGE * STAGE_BYTES + 256)      // 61696

// Device-global scratch (allocation-free rule)
__device__ __half g_Aq[GEMM_M * GEMM_K];   // 4 MB: fp16(q)
__device__ __half g_Wt[GEMM_N * GEMM_K];   // 2 MB: Wt fp16 (N-major, K contiguous)

// ---------------------------------------------------------------------------
// helpers
// ---------------------------------------------------------------------------
__device__ __forceinline__ uint32_t smem_u32(const void* p) {
    uint32_t a;
    asm("{ .reg .u64 t; cvta.to.shared.u64 t, %1; cvt.u32.u64 %0, t; }"
        : "=r"(a) : "l"(p));
    return a;
}

__device__ __forceinline__ void ldsm_x4(uint32_t* r, uint32_t addr) {
    asm volatile("ldmatrix.sync.aligned.m8n8.x4.shared.b16 {%0,%1,%2,%3}, [%4];"
                 : "=r"(r[0]), "=r"(r[1]), "=r"(r[2]), "=r"(r[3]) : "r"(addr));
}

__device__ __forceinline__ void mma16816(float* c, const uint32_t* a,
                                         const uint32_t* b) {
    asm volatile(
        "mma.sync.aligned.m16n8k16.row.col.f32.f16.f16.f32 "
        "{%0,%1,%2,%3}, {%4,%5,%6,%7}, {%8,%9}, {%0,%1,%2,%3};"
        : "+f"(c[0]), "+f"(c[1]), "+f"(c[2]), "+f"(c[3])
        : "r"(a[0]), "r"(a[1]), "r"(a[2]), "r"(a[3]), "r"(b[0]), "r"(b[1]));
}

#define CP_ASYNC16(dst, src) \
    asm volatile("cp.async.cg.shared.global [%0], [%1], 16;" \
                 :: "r"(dst), "l"(src) : "memory")
#define CP_COMMIT() asm volatile("cp.async.commit_group;" ::: "memory")
#define CP_WAIT(n)  asm volatile("cp.async.wait_group %0;" :: "n"(n) : "memory")

__device__ __forceinline__ float sgnf(float v) {
    return (v > 0.f) ? 1.f : ((v < 0.f) ? -1.f : 0.f);
}

// ----------------------------------------------------------------------------
// Kernel 1: quantize activations -> fp16 integers q (coalesced grid-stride)
// ----------------------------------------------------------------------------
#define QBLOCKS 512
#define QITERS  4    // 512*256*4 = 524288 float4s = 2048*1024 floats

__global__ __launch_bounds__(256) void quant_kernel(
    const float* __restrict__ x,
    const float* __restrict__ act_scale,
    __half* __restrict__ qout)
{
    const float s = fmaxf(fabsf(act_scale[0]), 1e-8f);
    const float inv = 1.0f / s;
    const int stride = QBLOCKS * 256;
    int i = blockIdx.x * 256 + threadIdx.x;
    const float4* xv = (const float4*)x;
    __half2* o = (__half2*)qout;
    #pragma unroll
    for (int t = 0; t < QITERS; ++t, i += stride) {
        float4 v = xv[i];
        float q0 = fminf(fmaxf(rintf(v.x * inv), -127.f), 127.f);
        float q1 = fminf(fmaxf(rintf(v.y * inv), -127.f), 127.f);
        float q2 = fminf(fmaxf(rintf(v.z * inv), -127.f), 127.f);
        float q3 = fminf(fmaxf(rintf(v.w * inv), -127.f), 127.f);
        o[2 * i + 0] = __floats2half2_rn(q0, q1);
        o[2 * i + 1] = __floats2half2_rn(q2, q3);
    }
}

// ----------------------------------------------------------------------------
// Kernel 2: build Wt (N-major) as fp16.
//   Wt[n_glob = j*32+m][k_glob = k*32+n] = W[(k,n),(j,m)]
// ----------------------------------------------------------------------------
__global__ __launch_bounds__(256) void build_w_kernel(
    const float* __restrict__ Y,   // (p,j,k,m,l)
    const float* __restrict__ Z,   // (p,j,k,l,n)
    const float* __restrict__ A)   // (p,j,k,4)
{
    const int j = blockIdx.x;
    const int k = blockIdx.y;
    const int tid = threadIdx.x;

    __shared__ float sY[PP][MM * LL];
    __shared__ float sZ[PP][LL * NN];
    __shared__ float redY[256], redZ[256];
    __shared__ float ysh[PP], zsh[PP];
    __shared__ float aSh[PP][4];
    __shared__ float Ysum[PP][MM];
    __shared__ float Zsum[PP][NN];

    #pragma unroll
    for (int p = 0; p < PP; ++p) {
        size_t base = ((size_t)((p * JJ + j) * KK + k)) * 256;
        float y = Y[base + tid];
        float z = Z[base + tid];
        sY[p][tid] = sgnf(y);
        sZ[p][tid] = sgnf(z);
        redY[tid] = fabsf(y);
        redZ[tid] = fabsf(z);
        __syncthreads();
        #pragma unroll
        for (int s = 128; s > 0; s >>= 1) {
            if (tid < s) { redY[tid] += redY[tid + s]; redZ[tid] += redZ[tid + s]; }
            __syncthreads();
        }
        if (tid == 0) {
            ysh[p] = redY[0] * (1.0f / 256.0f);
            zsh[p] = redZ[0] * (1.0f / 256.0f);
        }
        __syncthreads();
    }

    if (tid < PP * 4) {
        int p = tid >> 2, c = tid & 3;
        aSh[p][c] = A[((size_t)(p * JJ + j) * KK + k) * 4 + c];
    }
    if (tid < 64) {
        int p = tid >> 5, m = tid & 31;
        float s = 0.f;
        #pragma unroll
        for (int l = 0; l < LL; ++l) s += sY[p][m * LL + l];
        Ysum[p][m] = s;
    } else if (tid < 128) {
        int t = tid - 64;
        int p = t >> 5, n = t & 31;
        float s = 0.f;
        #pragma unroll
        for (int l = 0; l < LL; ++l) s += sZ[p][l * NN + n];
        Zsum[p][n] = s;
    }
    __syncthreads();

    #pragma unroll
    for (int t = 0; t < 4; ++t) {
        int idx = t * 256 + tid;
        int m = idx >> 5;
        int n = idx & 31;
        float w = 0.f;
        #pragma unroll
        for (int p = 0; p < PP; ++p) {
            float dot = 0.f;
            #pragma unroll
            for (int l = 0; l < LL; ++l)
                dot += sY[p][m * LL + l] * sZ[p][l * NN + n];
            float ys = ysh[p], zs = zsh[p];
            w += aSh[p][0] * ys * zs * dot
               + aSh[p][1] * ys * Ysum[p][m]
               + aSh[p][2] * zs * Zsum[p][n]
               + aSh[p][3];
        }
        size_t off = (size_t)(j * MM + m) * GEMM_K + (k * NN + n);
        g_Wt[off] = __float2half_rn(w);
    }
}

// ----------------------------------------------------------------------------
// Kernel 3: mma.sync GEMM  out = s * (q @ Wt^T) + bias
// CTA 128x64, 8 warps (warp tile 32x32), BK=32, 4-stage cp.async pipeline,
// 2 CTAs/SM (grid 256 over 148 SMs, single wave).
// ----------------------------------------------------------------------------
extern __shared__ char dynsmem[];

__global__ __launch_bounds__(256, 2) void gemm_mma_kernel(
    const float* __restrict__ bias,
    const float* __restrict__ act_scale,
    float* __restrict__ out)
{
    const int tid  = threadIdx.x;
    const int wid  = tid >> 5;
    const int lane = tid & 31;
    const int n0 = blockIdx.x * BN;
    const int m0 = blockIdx.y * BM;

    const int warp_m = wid & 3;    // rows warp_m*32 (4 tiles x 32 = 128)
    const int warp_n = wid >> 2;   // cols warp_n*32 (2 tiles x 32 = 64)

    uint32_t raw = smem_u32(dynsmem);
    uint32_t sbase = (raw + 127u) & ~127u;

    const __half* Aq = g_Aq + (size_t)m0 * GEMM_K;
    const __half* Wp = g_Wt + (size_t)n0 * GEMM_K;

    // ---- async loader: chunk c -> stage buf ----
    // 192 rows (128 A + 64 B) x 4 segments of 16B = 768 cp.async, 3/thread
    auto load_chunk = [&](int c, int buf) {
        const int k0 = c * BKC;
        uint32_t base = sbase + buf * STAGE_BYTES;
        #pragma unroll
        for (int it = 0; it < 3; ++it) {
            int s = it * 256 + tid;       // 0..767
            int row = s >> 2;             // 0..191
            int seg = s & 3;              // 0..3
            uint32_t dst = base + (uint32_t)(row * (SM_STRIDE * 2) + seg * 16);
            if (row < BM) {
                size_t goff = (size_t)row * GEMM_K + k0 + seg * 8;
                CP_ASYNC16(dst, Aq + goff);
            } else {
                size_t goff = (size_t)(row - BM) * GEMM_K + k0 + seg * 8;
                CP_ASYNC16(dst, Wp + goff);
            }
        }
    };

    float acc[2][4][4];
    #pragma unroll
    for (int mi = 0; mi < 2; ++mi)
        #pragma unroll
        for (int ni = 0; ni < 4; ++ni)
            #pragma unroll
            for (int q = 0; q < 4; ++q) acc[mi][ni][q] = 0.f;

    // ldmatrix thread mappings
    const int aRowT = warp_m * 32 + (lane & 15);   // + mi*16
    const int aKT   = (lane >> 4) * 8;
    const int grp = lane >> 3, ln = lane & 7;
    const int bRowBase = BM + warp_n * 32 + (grp >> 1) * 8 + ln;  // + half*16
    const int bKT = (grp & 1) * 8;

    // prologue: stages 0..2
    load_chunk(0, 0); CP_COMMIT();
    load_chunk(1, 1); CP_COMMIT();
    load_chunk(2, 2); CP_COMMIT();

    for (int c = 0; c < NCHUNK; ++c) {
        const int buf = c & 3;
        if (c < NCHUNK - 2)      { CP_WAIT(2); }
        else if (c == NCHUNK - 2){ CP_WAIT(1); }
        else                     { CP_WAIT(0); }
        __syncthreads();

        if (c + 3 < NCHUNK) {
            load_chunk(c + 3, (c + 3) & 3);
            CP_COMMIT();
        }

        const uint32_t stg = sbase + buf * STAGE_BYTES;

        #pragma unroll
        for (int ks = 0; ks < BKC; ks += 16) {
            uint32_t afrag[2][4];
            #pragma unroll
            for (int mi = 0; mi < 2; ++mi) {
                uint32_t addr = stg +
                    (uint32_t)((aRowT + mi * 16) * (SM_STRIDE * 2) + (ks + aKT) * 2);
                ldsm_x4(afrag[mi], addr);
            }
            uint32_t bf[4][2];
            #pragma unroll
            for (int half = 0; half < 2; ++half) {
                uint32_t r[4];
                uint32_t addr = stg +
                    (uint32_t)((bRowBase + half * 16) * (SM_STRIDE * 2) + (ks + bKT) * 2);
                ldsm_x4(r, addr);
                bf[2 * half][0] = r[0]; bf[2 * half][1] = r[1];
                bf[2 * half + 1][0] = r[2]; bf[2 * half + 1][1] = r[3];
            }
            #pragma unroll
            for (int mi = 0; mi < 2; ++mi)
                #pragma unroll
                for (int ni = 0; ni < 4; ++ni)
                    mma16816(acc[mi][ni], afrag[mi], bf[ni]);
        }
    }

    // ---- epilogue: out = acc*s + bias ----
    const float sval = fmaxf(fabsf(act_scale[0]), 1e-8f);
    const int gID = lane >> 2;
    const int tig = lane & 3;

    #pragma unroll
    for (int mi = 0; mi < 2; ++mi) {
        const int rbase = m0 + warp_m * 32 + mi * 16 + gID;
        #pragma unroll
        for (int ni = 0; ni < 4; ++ni) {
            const int col = n0 + warp_n * 32 + ni * 8 + 2 * tig;
            const float b0 = bias[col], b1 = bias[col + 1];
            float2 v0, v1;
            v0.x = acc[mi][ni][0] * sval + b0;
            v0.y = acc[mi][ni][1] * sval + b1;
            v1.x = acc[mi][ni][2] * sval + b0;
            v1.y = acc[mi][ni][3] * sval + b1;
            *(float2*)(out + (size_t)rbase * GEMM_N + col) = v0;
            *(float2*)(out + (size_t)(rbase + 8) * GEMM_N + col) = v1;
        }
    }
}

// ----------------------------------------------------------------------------
// Launch. Inputs (metadata order): x, Y_fp, Z_fp, A, bias, act_scale
// ----------------------------------------------------------------------------
extern "C" void kernel_launch(void* const* d_in, const int* in_sizes, int n_in,
                              void* d_out, int out_size) {
    const float* x         = (const float*)d_in[0];
    const float* Y_fp      = (const float*)d_in[1];
    const float* Z_fp      = (const float*)d_in[2];
    const float* A         = (const float*)d_in[3];
    const float* bias      = (const float*)d_in[4];
    const float* act_scale = (const float*)d_in[5];
    float* out = (float*)d_out;

    __half* aq;
    cudaGetSymbolAddress((void**)&aq, g_Aq);

    cudaFuncSetAttribute(gemm_mma_kernel,
                         cudaFuncAttributeMaxDynamicSharedMemorySize, DSMEM_BYTES);

    quant_kernel<<<QBLOCKS, 256>>>(x, act_scale, aq);

    dim3 gridW(JJ, KK);
    build_w_kernel<<<gridW, 256>>>(Y_fp, Z_fp, A);

    dim3 gridG(GEMM_N / BN, GEMM_M / BM);
    gemm_mma_kernel<<<gridG, 256, DSMEM_BYTES>>>(bias, act_scale, out);
}

// round 9
// speedup vs baseline: 5.2646x; 1.1405x over previous
#include <cuda_runtime.h>
#include <cuda_fp16.h>
#include <cstdint>

// ============================================================================
// BQQLinear collapsed to:  out = quant8(x) @ W + bias
//   quant8(x) = s * q,  q integer in [-127,127]  -> q exact in fp16
//   W (fp32) -> fp16 ;  out = s * ( q @ W_fp16 ) + bias
// GEMM via mma.sync m16n8k16 f16 (fp32 accum), compute_103-safe PTX.
//   X: (M=2048, K=1024), Wt (N=1024, K=1024) K-major
// ============================================================================

#define PP 2
#define JJ 32
#define KK 32
#define MM 32
#define LL 8
#define NN 32

#define GEMM_M 2048
#define GEMM_N 1024
#define GEMM_K 1024

#define BM 128
#define BN 64
#define BKC 32
#define NCHUNK (GEMM_K / BKC)      // 32

#define SM_STRIDE 40               // fp16 elems per smem row (32 + 8 pad) -> 80 B
#define A_TILE_BYTES (BM * SM_STRIDE * 2)             // 10240
#define B_TILE_BYTES (BN * SM_STRIDE * 2)             // 5120
#define STAGE_BYTES (A_TILE_BYTES + B_TILE_BYTES)     // 15360
#define NSTAGE 4
#define DSMEM_BYTES (NSTAGE * STAGE_BYTES + 256)      // 61696

#define NTHREADS 128               // 4 warps, warp tile 64x32

// Device-global scratch (allocation-free rule)
__device__ __half g_Aq[GEMM_M * GEMM_K];   // 4 MB: fp16(q)
__device__ __half g_Wt[GEMM_N * GEMM_K];   // 2 MB: Wt fp16 (N-major, K contiguous)

// ---------------------------------------------------------------------------
// helpers
// ---------------------------------------------------------------------------
__device__ __forceinline__ uint32_t smem_u32(const void* p) {
    uint32_t a;
    asm("{ .reg .u64 t; cvta.to.shared.u64 t, %1; cvt.u32.u64 %0, t; }"
        : "=r"(a) : "l"(p));
    return a;
}

__device__ __forceinline__ void ldsm_x4(uint32_t* r, uint32_t addr) {
    asm volatile("ldmatrix.sync.aligned.m8n8.x4.shared.b16 {%0,%1,%2,%3}, [%4];"
                 : "=r"(r[0]), "=r"(r[1]), "=r"(r[2]), "=r"(r[3]) : "r"(addr));
}

__device__ __forceinline__ void mma16816(float* c, const uint32_t* a,
                                         const uint32_t* b) {
    asm volatile(
        "mma.sync.aligned.m16n8k16.row.col.f32.f16.f16.f32 "
        "{%0,%1,%2,%3}, {%4,%5,%6,%7}, {%8,%9}, {%0,%1,%2,%3};"
        : "+f"(c[0]), "+f"(c[1]), "+f"(c[2]), "+f"(c[3])
        : "r"(a[0]), "r"(a[1]), "r"(a[2]), "r"(a[3]), "r"(b[0]), "r"(b[1]));
}

#define CP_ASYNC16(dst, src) \
    asm volatile("cp.async.cg.shared.global [%0], [%1], 16;" \
                 :: "r"(dst), "l"(src) : "memory")
#define CP_COMMIT() asm volatile("cp.async.commit_group;" ::: "memory")
#define CP_WAIT(n)  asm volatile("cp.async.wait_group %0;" :: "n"(n) : "memory")

__device__ __forceinline__ float sgnf(float v) {
    return (v > 0.f) ? 1.f : ((v < 0.f) ? -1.f : 0.f);
}

// ----------------------------------------------------------------------------
// Kernel 1 (fused prep):
//   blocks [0, 1024)        : build Wt (N-major fp16) for (j,k) pair
//   blocks [1024, 1024+2048): quantize x -> fp16 q (1 float4 per thread)
// ----------------------------------------------------------------------------
#define QBLOCKS 2048

__global__ __launch_bounds__(256) void prep_kernel(
    const float* __restrict__ x,
    const float* __restrict__ Y,   // (p,j,k,m,l)
    const float* __restrict__ Z,   // (p,j,k,l,n)
    const float* __restrict__ A,   // (p,j,k,4)
    const float* __restrict__ act_scale)
{
    const int tid = threadIdx.x;

    if (blockIdx.x >= 1024) {
        // ---- quant branch ----
        const float s = fmaxf(fabsf(act_scale[0]), 1e-8f);
        const float inv = 1.0f / s;
        int i = (blockIdx.x - 1024) * 256 + tid;     // float4 index
        float4 v = ((const float4*)x)[i];
        float q0 = fminf(fmaxf(rintf(v.x * inv), -127.f), 127.f);
        float q1 = fminf(fmaxf(rintf(v.y * inv), -127.f), 127.f);
        float q2 = fminf(fmaxf(rintf(v.z * inv), -127.f), 127.f);
        float q3 = fminf(fmaxf(rintf(v.w * inv), -127.f), 127.f);
        __half2* o = (__half2*)g_Aq;
        o[2 * i + 0] = __floats2half2_rn(q0, q1);
        o[2 * i + 1] = __floats2half2_rn(q2, q3);
        return;
    }

    // ---- W-build branch ----
    const int j = blockIdx.x >> 5;
    const int k = blockIdx.x & 31;

    __shared__ float sY[PP][MM * LL];
    __shared__ float sZ[PP][LL * NN];
    __shared__ float redY[256], redZ[256];
    __shared__ float ysh[PP], zsh[PP];
    __shared__ float aSh[PP][4];
    __shared__ float Ysum[PP][MM];
    __shared__ float Zsum[PP][NN];

    #pragma unroll
    for (int p = 0; p < PP; ++p) {
        size_t base = ((size_t)((p * JJ + j) * KK + k)) * 256;
        float y = Y[base + tid];
        float z = Z[base + tid];
        sY[p][tid] = sgnf(y);
        sZ[p][tid] = sgnf(z);
        redY[tid] = fabsf(y);
        redZ[tid] = fabsf(z);
        __syncthreads();
        #pragma unroll
        for (int s = 128; s > 0; s >>= 1) {
            if (tid < s) { redY[tid] += redY[tid + s]; redZ[tid] += redZ[tid + s]; }
            __syncthreads();
        }
        if (tid == 0) {
            ysh[p] = redY[0] * (1.0f / 256.0f);
            zsh[p] = redZ[0] * (1.0f / 256.0f);
        }
        __syncthreads();
    }

    if (tid < PP * 4) {
        int p = tid >> 2, c = tid & 3;
        aSh[p][c] = A[((size_t)(p * JJ + j) * KK + k) * 4 + c];
    }
    if (tid < 64) {
        int p = tid >> 5, m = tid & 31;
        float s = 0.f;
        #pragma unroll
        for (int l = 0; l < LL; ++l) s += sY[p][m * LL + l];
        Ysum[p][m] = s;
    } else if (tid < 128) {
        int t = tid - 64;
        int p = t >> 5, n = t & 31;
        float s = 0.f;
        #pragma unroll
        for (int l = 0; l < LL; ++l) s += sZ[p][l * NN + n];
        Zsum[p][n] = s;
    }
    __syncthreads();

    #pragma unroll
    for (int t = 0; t < 4; ++t) {
        int idx = t * 256 + tid;
        int m = idx >> 5;
        int n = idx & 31;
        float w = 0.f;
        #pragma unroll
        for (int p = 0; p < PP; ++p) {
            float dot = 0.f;
            #pragma unroll
            for (int l = 0; l < LL; ++l)
                dot += sY[p][m * LL + l] * sZ[p][l * NN + n];
            float ys = ysh[p], zs = zsh[p];
            w += aSh[p][0] * ys * zs * dot
               + aSh[p][1] * ys * Ysum[p][m]
               + aSh[p][2] * zs * Zsum[p][n]
               + aSh[p][3];
        }
        size_t off = (size_t)(j * MM + m) * GEMM_K + (k * NN + n);
        g_Wt[off] = __float2half_rn(w);
    }
}

// ----------------------------------------------------------------------------
// Kernel 2: mma.sync GEMM  out = s * (q @ Wt^T) + bias
// CTA 128x64, 4 warps (warp tile 64x32), BK=32, 4-stage cp.async pipeline.
// 128 threads/CTA -> up to 3 CTAs/SM by smem; grid 256 over 148 SMs.
// ----------------------------------------------------------------------------
extern __shared__ char dynsmem[];

__global__ __launch_bounds__(NTHREADS, 2) void gemm_mma_kernel(
    const float* __restrict__ bias,
    const float* __restrict__ act_scale,
    float* __restrict__ out)
{
    const int tid  = threadIdx.x;
    const int wid  = tid >> 5;
    const int lane = tid & 31;
    const int n0 = blockIdx.x * BN;
    const int m0 = blockIdx.y * BM;

    const int warp_m = wid & 1;    // rows warp_m*64 (2 x 64 = 128)
    const int warp_n = wid >> 1;   // cols warp_n*32 (2 x 32 = 64)

    uint32_t raw = smem_u32(dynsmem);
    uint32_t sbase = (raw + 127u) & ~127u;

    const __half* Aq = g_Aq + (size_t)m0 * GEMM_K;
    const __half* Wp = g_Wt + (size_t)n0 * GEMM_K;

    // ---- async loader: chunk c -> stage buf ----
    // 192 rows (128 A + 64 B) x 4 segments of 16B = 768 cp.async, 6/thread
    auto load_chunk = [&](int c, int buf) {
        const int k0 = c * BKC;
        uint32_t base = sbase + buf * STAGE_BYTES;
        #pragma unroll
        for (int it = 0; it < 6; ++it) {
            int s = it * NTHREADS + tid;  // 0..767
            int row = s >> 2;             // 0..191
            int seg = s & 3;              // 0..3
            uint32_t dst = base + (uint32_t)(row * (SM_STRIDE * 2) + seg * 16);
            if (row < BM) {
                size_t goff = (size_t)row * GEMM_K + k0 + seg * 8;
                CP_ASYNC16(dst, Aq + goff);
            } else {
                size_t goff = (size_t)(row - BM) * GEMM_K + k0 + seg * 8;
                CP_ASYNC16(dst, Wp + goff);
            }
        }
    };

    float acc[4][4][4];
    #pragma unroll
    for (int mi = 0; mi < 4; ++mi)
        #pragma unroll
        for (int ni = 0; ni < 4; ++ni)
            #pragma unroll
            for (int q = 0; q < 4; ++q) acc[mi][ni][q] = 0.f;

    // ldmatrix thread mappings
    const int aRowT = warp_m * 64 + (lane & 15);   // + mi*16
    const int aKT   = (lane >> 4) * 8;
    const int grp = lane >> 3, ln = lane & 7;
    const int bRowBase = BM + warp_n * 32 + (grp >> 1) * 8 + ln;  // + half*16
    const int bKT = (grp & 1) * 8;

    // prologue: stages 0..2
    load_chunk(0, 0); CP_COMMIT();
    load_chunk(1, 1); CP_COMMIT();
    load_chunk(2, 2); CP_COMMIT();

    for (int c = 0; c < NCHUNK; ++c) {
        const int buf = c & 3;
        if (c < NCHUNK - 2)      { CP_WAIT(2); }
        else if (c == NCHUNK - 2){ CP_WAIT(1); }
        else                     { CP_WAIT(0); }
        __syncthreads();

        if (c + 3 < NCHUNK) {
            load_chunk(c + 3, (c + 3) & 3);
            CP_COMMIT();
        }

        const uint32_t stg = sbase + buf * STAGE_BYTES;

        #pragma unroll
        for (int ks = 0; ks < BKC; ks += 16) {
            uint32_t afrag[4][4];
            #pragma unroll
            for (int mi = 0; mi < 4; ++mi) {
                uint32_t addr = stg +
                    (uint32_t)((aRowT + mi * 16) * (SM_STRIDE * 2) + (ks + aKT) * 2);
                ldsm_x4(afrag[mi], addr);
            }
            uint32_t bf[4][2];
            #pragma unroll
            for (int half = 0; half < 2; ++half) {
                uint32_t r[4];
                uint32_t addr = stg +
                    (uint32_t)((bRowBase + half * 16) * (SM_STRIDE * 2) + (ks + bKT) * 2);
                ldsm_x4(r, addr);
                bf[2 * half][0] = r[0]; bf[2 * half][1] = r[1];
                bf[2 * half + 1][0] = r[2]; bf[2 * half + 1][1] = r[3];
            }
            #pragma unroll
            for (int mi = 0; mi < 4; ++mi)
                #pragma unroll
                for (int ni = 0; ni < 4; ++ni)
                    mma16816(acc[mi][ni], afrag[mi], bf[ni]);
        }
    }

    // ---- epilogue: out = acc*s + bias ----
    const float sval = fmaxf(fabsf(act_scale[0]), 1e-8f);
    const int gID = lane >> 2;
    const int tig = lane & 3;

    #pragma unroll
    for (int mi = 0; mi < 4; ++mi) {
        const int rbase = m0 + warp_m * 64 + mi * 16 + gID;
        #pragma unroll
        for (int ni = 0; ni < 4; ++ni) {
            const int col = n0 + warp_n * 32 + ni * 8 + 2 * tig;
            const float b0 = bias[col], b1 = bias[col + 1];
            float2 v0, v1;
            v0.x = acc[mi][ni][0] * sval + b0;
            v0.y = acc[mi][ni][1] * sval + b1;
            v1.x = acc[mi][ni][2] * sval + b0;
            v1.y = acc[mi][ni][3] * sval + b1;
            *(float2*)(out + (size_t)rbase * GEMM_N + col) = v0;
            *(float2*)(out + (size_t)(rbase + 8) * GEMM_N + col) = v1;
        }
    }
}

// ----------------------------------------------------------------------------
// Launch. Inputs (metadata order): x, Y_fp, Z_fp, A, bias, act_scale
// ----------------------------------------------------------------------------
extern "C" void kernel_launch(void* const* d_in, const int* in_sizes, int n_in,
                              void* d_out, int out_size) {
    const float* x         = (const float*)d_in[0];
    const float* Y_fp      = (const float*)d_in[1];
    const float* Z_fp      = (const float*)d_in[2];
    const float* A         = (const float*)d_in[3];
    const float* bias      = (const float*)d_in[4];
    const float* act_scale = (const float*)d_in[5];
    float* out = (float*)d_out;

    cudaFuncSetAttribute(gemm_mma_kernel,
                         cudaFuncAttributeMaxDynamicSharedMemorySize, DSMEM_BYTES);

    // fused prep: W-build (1024 blocks) + quant (2048 blocks)
    prep_kernel<<<1024 + QBLOCKS, 256>>>(x, Y_fp, Z_fp, A, act_scale);

    dim3 gridG(GEMM_N / BN, GEMM_M / BM);
    gemm_mma_kernel<<<gridG, NTHREADS, DSMEM_BYTES>>>(bias, act_scale, out);
}

// round 10
// speedup vs baseline: 5.6283x; 1.0691x over previous
#include <cuda_runtime.h>
#include <cuda_fp16.h>
#include <cstdint>

// ============================================================================
// BQQLinear collapsed to:  out = quant8(x) @ W + bias
//   quant8(x) = s * q,  q integer in [-127,127]  -> q exact in fp16
//   W (fp32) -> fp16 ;  out = s * ( q @ W_fp16 ) + bias
// GEMM via mma.sync m16n8k16 f16 (fp32 accum), compute_103-safe PTX.
//   X: (M=2048, K=1024), Wt (N=1024, K=1024) K-major
// ============================================================================

#define PP 2
#define JJ 32
#define KK 32
#define MM 32
#define LL 8
#define NN 32

#define GEMM_M 2048
#define GEMM_N 1024
#define GEMM_K 1024

#define BM 128
#define BN 64
#define BKC 64
#define NCHUNK (GEMM_K / BKC)      // 16

#define SM_STRIDE 72               // fp16/row (64 + 8 pad) -> 144 B
#define A_TILE_BYTES (BM * SM_STRIDE * 2)             // 18432
#define B_TILE_BYTES (BN * SM_STRIDE * 2)             // 9216
#define STAGE_BYTES (A_TILE_BYTES + B_TILE_BYTES)     // 27648
#define NSTAGE 3
#define DSMEM_BYTES (NSTAGE * STAGE_BYTES + 256)      // 83200

#define NTHREADS 128               // 4 warps, warp tile 64x32

// Device-global scratch (allocation-free rule)
__device__ __half g_Aq[GEMM_M * GEMM_K];   // 4 MB: fp16(q)
__device__ __half g_Wt[GEMM_N * GEMM_K];   // 2 MB: Wt fp16 (N-major, K contiguous)

// ---------------------------------------------------------------------------
// helpers
// ---------------------------------------------------------------------------
__device__ __forceinline__ uint32_t smem_u32(const void* p) {
    uint32_t a;
    asm("{ .reg .u64 t; cvta.to.shared.u64 t, %1; cvt.u32.u64 %0, t; }"
        : "=r"(a) : "l"(p));
    return a;
}

__device__ __forceinline__ void ldsm_x4(uint32_t* r, uint32_t addr) {
    asm volatile("ldmatrix.sync.aligned.m8n8.x4.shared.b16 {%0,%1,%2,%3}, [%4];"
                 : "=r"(r[0]), "=r"(r[1]), "=r"(r[2]), "=r"(r[3]) : "r"(addr));
}

__device__ __forceinline__ void mma16816(float* c, const uint32_t* a,
                                         const uint32_t* b) {
    asm volatile(
        "mma.sync.aligned.m16n8k16.row.col.f32.f16.f16.f32 "
        "{%0,%1,%2,%3}, {%4,%5,%6,%7}, {%8,%9}, {%0,%1,%2,%3};"
        : "+f"(c[0]), "+f"(c[1]), "+f"(c[2]), "+f"(c[3])
        : "r"(a[0]), "r"(a[1]), "r"(a[2]), "r"(a[3]), "r"(b[0]), "r"(b[1]));
}

#define CP_ASYNC16(dst, src) \
    asm volatile("cp.async.cg.shared.global [%0], [%1], 16;" \
                 :: "r"(dst), "l"(src) : "memory")
#define CP_COMMIT() asm volatile("cp.async.commit_group;" ::: "memory")
#define CP_WAIT(n)  asm volatile("cp.async.wait_group %0;" :: "n"(n) : "memory")

__device__ __forceinline__ float sgnf(float v) {
    return (v > 0.f) ? 1.f : ((v < 0.f) ? -1.f : 0.f);
}

// ----------------------------------------------------------------------------
// Kernel 1 (fused prep):
//   blocks [0, 1024)        : build Wt (N-major fp16) for (j,k) pair
//   blocks [1024, 2048)     : quantize x -> fp16 q (2 float4 per thread)
// ----------------------------------------------------------------------------
#define QBLOCKS 1024

__global__ __launch_bounds__(256) void prep_kernel(
    const float* __restrict__ x,
    const float* __restrict__ Y,   // (p,j,k,m,l)
    const float* __restrict__ Z,   // (p,j,k,l,n)
    const float* __restrict__ A,   // (p,j,k,4)
    const float* __restrict__ act_scale)
{
    const int tid = threadIdx.x;

    if (blockIdx.x >= 1024) {
        // ---- quant branch ----
        const float s = fmaxf(fabsf(act_scale[0]), 1e-8f);
        const float inv = 1.0f / s;
        const float4* xv = (const float4*)x;
        __half2* o = (__half2*)g_Aq;
        int i = (blockIdx.x - 1024) * 256 + tid;   // float4 index
        #pragma unroll
        for (int t = 0; t < 2; ++t, i += QBLOCKS * 256) {
            float4 v = xv[i];
            float q0 = fminf(fmaxf(rintf(v.x * inv), -127.f), 127.f);
            float q1 = fminf(fmaxf(rintf(v.y * inv), -127.f), 127.f);
            float q2 = fminf(fmaxf(rintf(v.z * inv), -127.f), 127.f);
            float q3 = fminf(fmaxf(rintf(v.w * inv), -127.f), 127.f);
            o[2 * i + 0] = __floats2half2_rn(q0, q1);
            o[2 * i + 1] = __floats2half2_rn(q2, q3);
        }
        return;
    }

    // ---- W-build branch ----
    const int j = blockIdx.x >> 5;
    const int k = blockIdx.x & 31;
    const int lane = tid & 31;
    const int wrp  = tid >> 5;

    __shared__ float sY[PP][MM * LL];
    __shared__ float sZ[PP][LL * NN];
    __shared__ float wpY[PP][8], wpZ[PP][8];
    __shared__ float ysh[PP], zsh[PP];
    __shared__ float aSh[PP][4];
    __shared__ float Ysum[PP][MM];
    __shared__ float Zsum[PP][NN];

    #pragma unroll
    for (int p = 0; p < PP; ++p) {
        size_t base = ((size_t)((p * JJ + j) * KK + k)) * 256;
        float y = Y[base + tid];
        float z = Z[base + tid];
        sY[p][tid] = sgnf(y);
        sZ[p][tid] = sgnf(z);
        float ay = fabsf(y), az = fabsf(z);
        #pragma unroll
        for (int off = 16; off > 0; off >>= 1) {
            ay += __shfl_xor_sync(0xFFFFFFFFu, ay, off);
            az += __shfl_xor_sync(0xFFFFFFFFu, az, off);
        }
        if (lane == 0) { wpY[p][wrp] = ay; wpZ[p][wrp] = az; }
    }
    __syncthreads();
    if (tid < PP) {
        float sy = 0.f, sz = 0.f;
        #pragma unroll
        for (int w = 0; w < 8; ++w) { sy += wpY[tid][w]; sz += wpZ[tid][w]; }
        ysh[tid] = sy * (1.0f / 256.0f);
        zsh[tid] = sz * (1.0f / 256.0f);
    }
    if (tid >= 32 && tid < 32 + PP * 4) {
        int t = tid - 32;
        int p = t >> 2, c = t & 3;
        aSh[p][c] = A[((size_t)(p * JJ + j) * KK + k) * 4 + c];
    }
    if (tid >= 64 && tid < 128) {
        int t = tid - 64;
        int p = t >> 5, m = t & 31;
        float s = 0.f;
        #pragma unroll
        for (int l = 0; l < LL; ++l) s += sY[p][m * LL + l];
        Ysum[p][m] = s;
    } else if (tid >= 128 && tid < 192) {
        int t = tid - 128;
        int p = t >> 5, n = t & 31;
        float s = 0.f;
        #pragma unroll
        for (int l = 0; l < LL; ++l) s += sZ[p][l * NN + n];
        Zsum[p][n] = s;
    }
    __syncthreads();

    #pragma unroll
    for (int t = 0; t < 4; ++t) {
        int idx = t * 256 + tid;
        int m = idx >> 5;
        int n = idx & 31;
        float w = 0.f;
        #pragma unroll
        for (int p = 0; p < PP; ++p) {
            float dot = 0.f;
            #pragma unroll
            for (int l = 0; l < LL; ++l)
                dot += sY[p][m * LL + l] * sZ[p][l * NN + n];
            float ys = ysh[p], zs = zsh[p];
            w += aSh[p][0] * ys * zs * dot
               + aSh[p][1] * ys * Ysum[p][m]
               + aSh[p][2] * zs * Zsum[p][n]
               + aSh[p][3];
        }
        size_t off = (size_t)(j * MM + m) * GEMM_K + (k * NN + n);
        g_Wt[off] = __float2half_rn(w);
    }
}

// ----------------------------------------------------------------------------
// Kernel 2: mma.sync GEMM  out = s * (q @ Wt^T) + bias
// CTA 128x64, 4 warps (warp tile 64x32), BK=64, 3-stage cp.async pipeline,
// register-fragment double buffering (LDSM of ks+1 overlaps MMA of ks).
// ----------------------------------------------------------------------------
extern __shared__ char dynsmem[];

__global__ __launch_bounds__(NTHREADS, 2) void gemm_mma_kernel(
    const float* __restrict__ bias,
    const float* __restrict__ act_scale,
    float* __restrict__ out)
{
    const int tid  = threadIdx.x;
    const int wid  = tid >> 5;
    const int lane = tid & 31;
    const int n0 = blockIdx.x * BN;
    const int m0 = blockIdx.y * BM;

    const int warp_m = wid & 1;    // rows warp_m*64
    const int warp_n = wid >> 1;   // cols warp_n*32

    uint32_t raw = smem_u32(dynsmem);
    uint32_t sbase = (raw + 127u) & ~127u;

    const __half* Aq = g_Aq + (size_t)m0 * GEMM_K;
    const __half* Wp = g_Wt + (size_t)n0 * GEMM_K;

    // ---- async loader: chunk c -> stage buf ----
    // 192 rows (128 A + 64 B) x 8 segments of 16B = 1536 cp.async, 12/thread
    auto load_chunk = [&](int c, int buf) {
        const int k0 = c * BKC;
        uint32_t base = sbase + buf * STAGE_BYTES;
        #pragma unroll
        for (int it = 0; it < 12; ++it) {
            int s = it * NTHREADS + tid;  // 0..1535
            int row = s >> 3;             // 0..191
            int seg = s & 7;              // 0..7
            uint32_t dst = base + (uint32_t)(row * (SM_STRIDE * 2) + seg * 16);
            if (row < BM) {
                size_t goff = (size_t)row * GEMM_K + k0 + seg * 8;
                CP_ASYNC16(dst, Aq + goff);
            } else {
                size_t goff = (size_t)(row - BM) * GEMM_K + k0 + seg * 8;
                CP_ASYNC16(dst, Wp + goff);
            }
        }
    };

    float acc[4][4][4];
    #pragma unroll
    for (int mi = 0; mi < 4; ++mi)
        #pragma unroll
        for (int ni = 0; ni < 4; ++ni)
            #pragma unroll
            for (int q = 0; q < 4; ++q) acc[mi][ni][q] = 0.f;

    // ldmatrix thread mappings
    const int aRowT = warp_m * 64 + (lane & 15);   // + mi*16
    const int aKT   = (lane >> 4) * 8;
    const int grp = lane >> 3, ln = lane & 7;
    const int bRowBase = BM + warp_n * 32 + (grp >> 1) * 8 + ln;  // + half*16
    const int bKT = (grp & 1) * 8;

    // fragment loader for one 16-wide k-step within stage 'stg'
    auto load_frags = [&](uint32_t stg, int ks, uint32_t af[4][4], uint32_t bf[4][2]) {
        #pragma unroll
        for (int mi = 0; mi < 4; ++mi) {
            uint32_t addr = stg +
                (uint32_t)((aRowT + mi * 16) * (SM_STRIDE * 2) + (ks + aKT) * 2);
            ldsm_x4(af[mi], addr);
        }
        #pragma unroll
        for (int half = 0; half < 2; ++half) {
            uint32_t r[4];
            uint32_t addr = stg +
                (uint32_t)((bRowBase + half * 16) * (SM_STRIDE * 2) + (ks + bKT) * 2);
            ldsm_x4(r, addr);
            bf[2 * half][0] = r[0]; bf[2 * half][1] = r[1];
            bf[2 * half + 1][0] = r[2]; bf[2 * half + 1][1] = r[3];
        }
    };

    // prologue: stages 0,1
    load_chunk(0, 0); CP_COMMIT();
    load_chunk(1, 1); CP_COMMIT();

    uint32_t afr[2][4][4], bfr[2][4][2];

    for (int c = 0; c < NCHUNK; ++c) {
        const int buf = c % NSTAGE;
        if (c < NCHUNK - 1) { CP_WAIT(1); } else { CP_WAIT(0); }
        __syncthreads();

        if (c + 2 < NCHUNK) {
            load_chunk(c + 2, (c + 2) % NSTAGE);
            CP_COMMIT();
        }

        const uint32_t stg = sbase + buf * STAGE_BYTES;

        // frag-pipelined inner loop: 4 k-steps of 16
        load_frags(stg, 0, afr[0], bfr[0]);
        #pragma unroll
        for (int ksi = 0; ksi < 4; ++ksi) {
            const int cur = ksi & 1;
            if (ksi < 3)
                load_frags(stg, (ksi + 1) * 16, afr[cur ^ 1], bfr[cur ^ 1]);
            #pragma unroll
            for (int mi = 0; mi < 4; ++mi)
                #pragma unroll
                for (int ni = 0; ni < 4; ++ni)
                    mma16816(acc[mi][ni], afr[cur][mi], bfr[cur][ni]);
        }
    }

    // ---- epilogue: out = acc*s + bias ----
    const float sval = fmaxf(fabsf(act_scale[0]), 1e-8f);
    const int gID = lane >> 2;
    const int tig = lane & 3;

    #pragma unroll
    for (int mi = 0; mi < 4; ++mi) {
        const int rbase = m0 + warp_m * 64 + mi * 16 + gID;
        #pragma unroll
        for (int ni = 0; ni < 4; ++ni) {
            const int col = n0 + warp_n * 32 + ni * 8 + 2 * tig;
            const float b0 = bias[col], b1 = bias[col + 1];
            float2 v0, v1;
            v0.x = acc[mi][ni][0] * sval + b0;
            v0.y = acc[mi][ni][1] * sval + b1;
            v1.x = acc[mi][ni][2] * sval + b0;
            v1.y = acc[mi][ni][3] * sval + b1;
            *(float2*)(out + (size_t)rbase * GEMM_N + col) = v0;
            *(float2*)(out + (size_t)(rbase + 8) * GEMM_N + col) = v1;
        }
    }
}

// ----------------------------------------------------------------------------
// Launch. Inputs (metadata order): x, Y_fp, Z_fp, A, bias, act_scale
// ----------------------------------------------------------------------------
extern "C" void kernel_launch(void* const* d_in, const int* in_sizes, int n_in,
                              void* d_out, int out_size) {
    const float* x         = (const float*)d_in[0];
    const float* Y_fp      = (const float*)d_in[1];
    const float* Z_fp      = (const float*)d_in[2];
    const float* A         = (const float*)d_in[3];
    const float* bias      = (const float*)d_in[4];
    const float* act_scale = (const float*)d_in[5];
    float* out = (float*)d_out;

    cudaFuncSetAttribute(gemm_mma_kernel,
                         cudaFuncAttributeMaxDynamicSharedMemorySize, DSMEM_BYTES);

    // fused prep: W-build (1024 blocks) + quant (1024 blocks)
    prep_kernel<<<1024 + QBLOCKS, 256>>>(x, Y_fp, Z_fp, A, act_scale);

    dim3 gridG(GEMM_N / BN, GEMM_M / BM);
    gemm_mma_kernel<<<gridG, NTHREADS, DSMEM_BYTES>>>(bias, act_scale, out);
}

// round 11
// speedup vs baseline: 6.5556x; 1.1648x over previous
#include <cuda_runtime.h>
#include <cuda_fp16.h>
#include <cstdint>

// ============================================================================
// BQQLinear collapsed to:  out = quant8(x) @ W + bias
//   quant8(x) = s * q,  q integer in [-127,127]  -> q exact in fp16
//   W (fp32) -> fp16 ;  out = s * ( q @ W_fp16 ) + bias
// GEMM via mma.sync m16n8k16 f16 (fp32 accum), compute_103-safe PTX.
// In-CTA warp-level split-K: 8 warps = 4 tile positions x 2 K-groups.
//   X: (M=2048, K=1024), Wt (N=1024, K=1024) K-major
// ============================================================================

#define PP 2
#define JJ 32
#define KK 32
#define MM 32
#define LL 8
#define NN 32

#define GEMM_M 2048
#define GEMM_N 1024
#define GEMM_K 1024

#define BM 128
#define BN 64
#define BKC 64
#define NCHUNK (GEMM_K / BKC)      // 16

#define SM_STRIDE 72               // fp16/row (64 + 8 pad) -> 144 B
#define A_TILE_BYTES (BM * SM_STRIDE * 2)             // 18432
#define B_TILE_BYTES (BN * SM_STRIDE * 2)             // 9216
#define STAGE_BYTES (A_TILE_BYTES + B_TILE_BYTES)     // 27648
#define NSTAGE 3
#define DSMEM_BYTES (NSTAGE * STAGE_BYTES + 256)      // 83200

#define NTHREADS 256               // 8 warps: 4 tiles (64x32) x 2 k-groups

// Device-global scratch (allocation-free rule)
__device__ __half g_Aq[GEMM_M * GEMM_K];   // 4 MB: fp16(q)
__device__ __half g_Wt[GEMM_N * GEMM_K];   // 2 MB: Wt fp16 (N-major, K contiguous)

// ---------------------------------------------------------------------------
// helpers
// ---------------------------------------------------------------------------
__device__ __forceinline__ uint32_t smem_u32(const void* p) {
    uint32_t a;
    asm("{ .reg .u64 t; cvta.to.shared.u64 t, %1; cvt.u32.u64 %0, t; }"
        : "=r"(a) : "l"(p));
    return a;
}

__device__ __forceinline__ void ldsm_x4(uint32_t* r, uint32_t addr) {
    asm volatile("ldmatrix.sync.aligned.m8n8.x4.shared.b16 {%0,%1,%2,%3}, [%4];"
                 : "=r"(r[0]), "=r"(r[1]), "=r"(r[2]), "=r"(r[3]) : "r"(addr));
}

__device__ __forceinline__ void mma16816(float* c, const uint32_t* a,
                                         const uint32_t* b) {
    asm volatile(
        "mma.sync.aligned.m16n8k16.row.col.f32.f16.f16.f32 "
        "{%0,%1,%2,%3}, {%4,%5,%6,%7}, {%8,%9}, {%0,%1,%2,%3};"
        : "+f"(c[0]), "+f"(c[1]), "+f"(c[2]), "+f"(c[3])
        : "r"(a[0]), "r"(a[1]), "r"(a[2]), "r"(a[3]), "r"(b[0]), "r"(b[1]));
}

#define CP_ASYNC16(dst, src) \
    asm volatile("cp.async.cg.shared.global [%0], [%1], 16;" \
                 :: "r"(dst), "l"(src) : "memory")
#define CP_COMMIT() asm volatile("cp.async.commit_group;" ::: "memory")
#define CP_WAIT(n)  asm volatile("cp.async.wait_group %0;" :: "n"(n) : "memory")

__device__ __forceinline__ float sgnf(float v) {
    return (v > 0.f) ? 1.f : ((v < 0.f) ? -1.f : 0.f);
}

// ----------------------------------------------------------------------------
// Kernel 1 (fused prep):
//   blocks [0, 1024)    : build Wt (N-major fp16) for (j,k) pair
//   blocks [1024, 2048) : quantize x -> fp16 q (2 float4 per thread)
// ----------------------------------------------------------------------------
#define QBLOCKS 1024

__global__ __launch_bounds__(256) void prep_kernel(
    const float* __restrict__ x,
    const float* __restrict__ Y,   // (p,j,k,m,l)
    const float* __restrict__ Z,   // (p,j,k,l,n)
    const float* __restrict__ A,   // (p,j,k,4)
    const float* __restrict__ act_scale)
{
    const int tid = threadIdx.x;

    if (blockIdx.x >= 1024) {
        // ---- quant branch ----
        const float s = fmaxf(fabsf(act_scale[0]), 1e-8f);
        const float inv = 1.0f / s;
        const float4* xv = (const float4*)x;
        __half2* o = (__half2*)g_Aq;
        int i = (blockIdx.x - 1024) * 256 + tid;   // float4 index
        #pragma unroll
        for (int t = 0; t < 2; ++t, i += QBLOCKS * 256) {
            float4 v = xv[i];
            float q0 = fminf(fmaxf(rintf(v.x * inv), -127.f), 127.f);
            float q1 = fminf(fmaxf(rintf(v.y * inv), -127.f), 127.f);
            float q2 = fminf(fmaxf(rintf(v.z * inv), -127.f), 127.f);
            float q3 = fminf(fmaxf(rintf(v.w * inv), -127.f), 127.f);
            o[2 * i + 0] = __floats2half2_rn(q0, q1);
            o[2 * i + 1] = __floats2half2_rn(q2, q3);
        }
        return;
    }

    // ---- W-build branch ----
    const int j = blockIdx.x >> 5;
    const int k = blockIdx.x & 31;
    const int lane = tid & 31;
    const int wrp  = tid >> 5;

    __shared__ float sY[PP][MM * LL];
    __shared__ float sZ[PP][LL * NN];
    __shared__ float wpY[PP][8], wpZ[PP][8];
    __shared__ float ysh[PP], zsh[PP];
    __shared__ float aSh[PP][4];
    __shared__ float Ysum[PP][MM];
    __shared__ float Zsum[PP][NN];

    #pragma unroll
    for (int p = 0; p < PP; ++p) {
        size_t base = ((size_t)((p * JJ + j) * KK + k)) * 256;
        float y = Y[base + tid];
        float z = Z[base + tid];
        sY[p][tid] = sgnf(y);
        sZ[p][tid] = sgnf(z);
        float ay = fabsf(y), az = fabsf(z);
        #pragma unroll
        for (int off = 16; off > 0; off >>= 1) {
            ay += __shfl_xor_sync(0xFFFFFFFFu, ay, off);
            az += __shfl_xor_sync(0xFFFFFFFFu, az, off);
        }
        if (lane == 0) { wpY[p][wrp] = ay; wpZ[p][wrp] = az; }
    }
    __syncthreads();
    if (tid < PP) {
        float sy = 0.f, sz = 0.f;
        #pragma unroll
        for (int w = 0; w < 8; ++w) { sy += wpY[tid][w]; sz += wpZ[tid][w]; }
        ysh[tid] = sy * (1.0f / 256.0f);
        zsh[tid] = sz * (1.0f / 256.0f);
    }
    if (tid >= 32 && tid < 32 + PP * 4) {
        int t = tid - 32;
        int p = t >> 2, c = t & 3;
        aSh[p][c] = A[((size_t)(p * JJ + j) * KK + k) * 4 + c];
    }
    if (tid >= 64 && tid < 128) {
        int t = tid - 64;
        int p = t >> 5, m = t & 31;
        float s = 0.f;
        #pragma unroll
        for (int l = 0; l < LL; ++l) s += sY[p][m * LL + l];
        Ysum[p][m] = s;
    } else if (tid >= 128 && tid < 192) {
        int t = tid - 128;
        int p = t >> 5, n = t & 31;
        float s = 0.f;
        #pragma unroll
        for (int l = 0; l < LL; ++l) s += sZ[p][l * NN + n];
        Zsum[p][n] = s;
    }
    __syncthreads();

    #pragma unroll
    for (int t = 0; t < 4; ++t) {
        int idx = t * 256 + tid;
        int m = idx >> 5;
        int n = idx & 31;
        float w = 0.f;
        #pragma unroll
        for (int p = 0; p < PP; ++p) {
            float dot = 0.f;
            #pragma unroll
            for (int l = 0; l < LL; ++l)
                dot += sY[p][m * LL + l] * sZ[p][l * NN + n];
            float ys = ysh[p], zs = zsh[p];
            w += aSh[p][0] * ys * zs * dot
               + aSh[p][1] * ys * Ysum[p][m]
               + aSh[p][2] * zs * Zsum[p][n]
               + aSh[p][3];
        }
        size_t off = (size_t)(j * MM + m) * GEMM_K + (k * NN + n);
        g_Wt[off] = __float2half_rn(w);
    }
}

// ----------------------------------------------------------------------------
// Kernel 2: mma.sync GEMM  out = s * (q @ Wt^T) + bias
// CTA 128x64, 8 warps: 4 tile positions (64x32) x 2 K-groups.
// Warp kg computes k in [kg*32, kg*32+32) of each 64-wide chunk.
// Final smem reduction pairs (tile, kg=0) <- (tile, kg=1), kg=0 does epilogue.
// ----------------------------------------------------------------------------
extern __shared__ char dynsmem[];

__global__ __launch_bounds__(NTHREADS, 2) void gemm_mma_kernel(
    const float* __restrict__ bias,
    const float* __restrict__ act_scale,
    float* __restrict__ out)
{
    const int tid  = threadIdx.x;
    const int wid  = tid >> 5;
    const int lane = tid & 31;
    const int n0 = blockIdx.x * BN;
    const int m0 = blockIdx.y * BM;

    const int warp_m = wid & 1;          // rows warp_m*64
    const int warp_n = (wid >> 1) & 1;   // cols warp_n*32
    const int kg     = wid >> 2;         // k-group: k in [kg*32, kg*32+32)

    uint32_t raw = smem_u32(dynsmem);
    uint32_t sbase = (raw + 127u) & ~127u;

    const __half* Aq = g_Aq + (size_t)m0 * GEMM_K;
    const __half* Wp = g_Wt + (size_t)n0 * GEMM_K;

    // ---- async loader: chunk c -> stage buf ----
    // 192 rows (128 A + 64 B) x 8 segments of 16B = 1536 cp.async, 6/thread
    auto load_chunk = [&](int c, int buf) {
        const int k0 = c * BKC;
        uint32_t base = sbase + buf * STAGE_BYTES;
        #pragma unroll
        for (int it = 0; it < 6; ++it) {
            int s = it * NTHREADS + tid;  // 0..1535
            int row = s >> 3;             // 0..191
            int seg = s & 7;              // 0..7
            uint32_t dst = base + (uint32_t)(row * (SM_STRIDE * 2) + seg * 16);
            if (row < BM) {
                size_t goff = (size_t)row * GEMM_K + k0 + seg * 8;
                CP_ASYNC16(dst, Aq + goff);
            } else {
                size_t goff = (size_t)(row - BM) * GEMM_K + k0 + seg * 8;
                CP_ASYNC16(dst, Wp + goff);
            }
        }
    };

    float acc[4][4][4];
    #pragma unroll
    for (int mi = 0; mi < 4; ++mi)
        #pragma unroll
        for (int ni = 0; ni < 4; ++ni)
            #pragma unroll
            for (int q = 0; q < 4; ++q) acc[mi][ni][q] = 0.f;

    // ldmatrix thread mappings (k offset includes kg*32)
    const int aRowT = warp_m * 64 + (lane & 15);   // + mi*16
    const int aKT   = (lane >> 4) * 8;
    const int grp = lane >> 3, ln = lane & 7;
    const int bRowBase = BM + warp_n * 32 + (grp >> 1) * 8 + ln;  // + half*16
    const int bKT = (grp & 1) * 8;
    const int kgOff = kg * 32;

    // prologue: stages 0,1
    load_chunk(0, 0); CP_COMMIT();
    load_chunk(1, 1); CP_COMMIT();

    for (int c = 0; c < NCHUNK; ++c) {
        const int buf = c % NSTAGE;
        if (c < NCHUNK - 1) { CP_WAIT(1); } else { CP_WAIT(0); }
        __syncthreads();

        if (c + 2 < NCHUNK) {
            load_chunk(c + 2, (c + 2) % NSTAGE);
            CP_COMMIT();
        }

        const uint32_t stg = sbase + buf * STAGE_BYTES;

        #pragma unroll
        for (int ksi = 0; ksi < 2; ++ksi) {
            const int ks = kgOff + ksi * 16;
            uint32_t afrag[4][4];
            #pragma unroll
            for (int mi = 0; mi < 4; ++mi) {
                uint32_t addr = stg +
                    (uint32_t)((aRowT + mi * 16) * (SM_STRIDE * 2) + (ks + aKT) * 2);
                ldsm_x4(afrag[mi], addr);
            }
            uint32_t bf[4][2];
            #pragma unroll
            for (int half = 0; half < 2; ++half) {
                uint32_t r[4];
                uint32_t addr = stg +
                    (uint32_t)((bRowBase + half * 16) * (SM_STRIDE * 2) + (ks + bKT) * 2);
                ldsm_x4(r, addr);
                bf[2 * half][0] = r[0]; bf[2 * half][1] = r[1];
                bf[2 * half + 1][0] = r[2]; bf[2 * half + 1][1] = r[3];
            }
            #pragma unroll
            for (int mi = 0; mi < 4; ++mi)
                #pragma unroll
                for (int ni = 0; ni < 4; ++ni)
                    mma16816(acc[mi][ni], afrag[mi], bf[ni]);
        }
    }

    // ---- split-K reduction: kg=1 warps -> smem, kg=0 warps add ----
    __syncthreads();   // all MMA smem reads complete; stage area reusable

    const int tile = wid & 3;   // 0..3, same for the (kg=0, kg=1) pair
    // layout: [tile][j (16)][lane (32)] float4  -> 8192 B per tile, 32 KB total
    const uint32_t red_base = sbase + (uint32_t)tile * 8192;

    if (kg == 1) {
        #pragma unroll
        for (int mi = 0; mi < 4; ++mi)
            #pragma unroll
            for (int ni = 0; ni < 4; ++ni) {
                int jj = mi * 4 + ni;
                uint32_t addr = red_base + (uint32_t)((jj * 32 + lane) * 16);
                asm volatile("st.shared.v4.b32 [%0], {%1,%2,%3,%4};"
                             :: "r"(addr),
                                "r"(__float_as_uint(acc[mi][ni][0])),
                                "r"(__float_as_uint(acc[mi][ni][1])),
                                "r"(__float_as_uint(acc[mi][ni][2])),
                                "r"(__float_as_uint(acc[mi][ni][3])) : "memory");
            }
    }
    __syncthreads();

    if (kg == 0) {
        const float sval = fmaxf(fabsf(act_scale[0]), 1e-8f);
        const int gID = lane >> 2;
        const int tig = lane & 3;

        #pragma unroll
        for (int mi = 0; mi < 4; ++mi) {
            const int rbase = m0 + warp_m * 64 + mi * 16 + gID;
            #pragma unroll
            for (int ni = 0; ni < 4; ++ni) {
                int jj = mi * 4 + ni;
                uint32_t addr = red_base + (uint32_t)((jj * 32 + lane) * 16);
                uint32_t r0, r1, r2, r3;
                asm volatile("ld.shared.v4.b32 {%0,%1,%2,%3}, [%4];"
                             : "=r"(r0), "=r"(r1), "=r"(r2), "=r"(r3) : "r"(addr));
                float a0 = acc[mi][ni][0] + __uint_as_float(r0);
                float a1 = acc[mi][ni][1] + __uint_as_float(r1);
                float a2 = acc[mi][ni][2] + __uint_as_float(r2);
                float a3 = acc[mi][ni][3] + __uint_as_float(r3);

                const int col = n0 + warp_n * 32 + ni * 8 + 2 * tig;
                const float b0 = bias[col], b1 = bias[col + 1];
                float2 v0, v1;
                v0.x = a0 * sval + b0;
                v0.y = a1 * sval + b1;
                v1.x = a2 * sval + b0;
                v1.y = a3 * sval + b1;
                *(float2*)(out + (size_t)rbase * GEMM_N + col) = v0;
                *(float2*)(out + (size_t)(rbase + 8) * GEMM_N + col) = v1;
            }
        }
    }
}

// ----------------------------------------------------------------------------
// Launch. Inputs (metadata order): x, Y_fp, Z_fp, A, bias, act_scale
// ----------------------------------------------------------------------------
extern "C" void kernel_launch(void* const* d_in, const int* in_sizes, int n_in,
                              void* d_out, int out_size) {
    const float* x         = (const float*)d_in[0];
    const float* Y_fp      = (const float*)d_in[1];
    const float* Z_fp      = (const float*)d_in[2];
    const float* A         = (const float*)d_in[3];
    const float* bias      = (const float*)d_in[4];
    const float* act_scale = (const float*)d_in[5];
    float* out = (float*)d_out;

    cudaFuncSetAttribute(gemm_mma_kernel,
                         cudaFuncAttributeMaxDynamicSharedMemorySize, DSMEM_BYTES);

    // fused prep: W-build (1024 blocks) + quant (1024 blocks)
    prep_kernel<<<1024 + QBLOCKS, 256>>>(x, Y_fp, Z_fp, A, act_scale);

    dim3 gridG(GEMM_N / BN, GEMM_M / BM);
    gemm_mma_kernel<<<gridG, NTHREADS, DSMEM_BYTES>>>(bias, act_scale, out);
}